// round 13
// baseline (speedup 1.0000x reference)
#include <cuda_runtime.h>
#include <cuda_bf16.h>
#include <math.h>
#include <stdint.h>

// ---------------------------------------------------------------------------
// Problem constants
// ---------------------------------------------------------------------------
#define BATCH   4
#define SEQ     2048
#define DIN     4096
#define DPROJ   512
#define DMEM    512
#define ASSIST  512
#define RUN     1536
#define ROWS    (BATCH*SEQ)   // 8192

// ---------------------------------------------------------------------------
// Device scratch
// ---------------------------------------------------------------------------
__device__ float g_Q[(size_t)ROWS*DPROJ];
__device__ float g_K[(size_t)ROWS*DPROJ];
__device__ float g_V[(size_t)ROWS*DPROJ];
__device__ float g_S[(size_t)BATCH*SEQ*SEQ];
__device__ float g_feat[(size_t)ROWS*DPROJ];
__device__ float g_Gz[(size_t)BATCH*RUN*DMEM];
__device__ float g_Gr[(size_t)BATCH*RUN*DMEM];
__device__ float g_Gh[(size_t)BATCH*RUN*DMEM];
__device__ float g_h[BATCH*DMEM];

// bf16 split operands for tensor-core QKV
__device__ __nv_bfloat16 g_xhi[(size_t)ROWS*DIN];
__device__ __nv_bfloat16 g_xlo[(size_t)ROWS*DIN];
__device__ __nv_bfloat16 g_Whi[3][(size_t)DIN*DPROJ];
__device__ __nv_bfloat16 g_Wlo[3][(size_t)DIN*DPROJ];

// ---------------------------------------------------------------------------
// Split fp32 -> (hi, lo) bf16.
// ---------------------------------------------------------------------------
__global__ void split_kernel(const float* __restrict__ src,
                             __nv_bfloat16* __restrict__ hi,
                             __nv_bfloat16* __restrict__ lo, size_t n4)
{
    size_t i = (size_t)blockIdx.x * blockDim.x + threadIdx.x;
    size_t stride = (size_t)gridDim.x * blockDim.x;
    for (; i < n4; i += stride) {
        float4 v = ((const float4*)src)[i];
        __nv_bfloat16 h0 = __float2bfloat16(v.x);
        __nv_bfloat16 h1 = __float2bfloat16(v.y);
        __nv_bfloat16 h2 = __float2bfloat16(v.z);
        __nv_bfloat16 h3 = __float2bfloat16(v.w);
        __nv_bfloat162 hh0 = {h0, h1}, hh1 = {h2, h3};
        __nv_bfloat162 ll0 = {__float2bfloat16(v.x - __bfloat162float(h0)),
                              __float2bfloat16(v.y - __bfloat162float(h1))};
        __nv_bfloat162 ll1 = {__float2bfloat16(v.z - __bfloat162float(h2)),
                              __float2bfloat16(v.w - __bfloat162float(h3))};
        ((__nv_bfloat162*)hi)[i * 2]     = hh0;
        ((__nv_bfloat162*)hi)[i * 2 + 1] = hh1;
        ((__nv_bfloat162*)lo)[i * 2]     = ll0;
        ((__nv_bfloat162*)lo)[i * 2 + 1] = ll1;
    }
}

// ---------------------------------------------------------------------------
// Tensor-core QKV GEMM (bf16x3) — unchanged from R11.
// ---------------------------------------------------------------------------
#define APITCH 40
#define BPITCH 136
#define SM_AHI 0
#define SM_ALO 20480
#define SM_BHI 40960
#define SM_BLO 58368
#define QKV_SMEM 75776

__device__ __forceinline__ uint32_t smem_addr_u32(const void* p) {
    uint32_t a;
    asm("{ .reg .u64 t; cvta.to.shared.u64 t, %1; cvt.u32.u64 %0, t; }"
        : "=r"(a) : "l"(p));
    return a;
}
__device__ __forceinline__ void ldsm_x4(uint32_t& r0, uint32_t& r1,
                                        uint32_t& r2, uint32_t& r3, uint32_t a) {
    asm volatile("ldmatrix.sync.aligned.m8n8.x4.shared.b16 {%0,%1,%2,%3}, [%4];"
                 : "=r"(r0), "=r"(r1), "=r"(r2), "=r"(r3) : "r"(a));
}
__device__ __forceinline__ void ldsm_x4_t(uint32_t& r0, uint32_t& r1,
                                          uint32_t& r2, uint32_t& r3, uint32_t a) {
    asm volatile("ldmatrix.sync.aligned.m8n8.x4.trans.shared.b16 {%0,%1,%2,%3}, [%4];"
                 : "=r"(r0), "=r"(r1), "=r"(r2), "=r"(r3) : "r"(a));
}
__device__ __forceinline__ void mma_bf16(float* d, const uint32_t* a,
                                         uint32_t b0, uint32_t b1) {
    asm volatile(
        "mma.sync.aligned.m16n8k16.row.col.f32.bf16.bf16.f32 "
        "{%0,%1,%2,%3}, {%4,%5,%6,%7}, {%8,%9}, {%0,%1,%2,%3};"
        : "+f"(d[0]), "+f"(d[1]), "+f"(d[2]), "+f"(d[3])
        : "r"(a[0]), "r"(a[1]), "r"(a[2]), "r"(a[3]), "r"(b0), "r"(b1));
}

__global__ void __launch_bounds__(256) qkv_mma_kernel(
    const __nv_bfloat16* __restrict__ Ah, const __nv_bfloat16* __restrict__ Al,
    const __nv_bfloat16* __restrict__ Bh, const __nv_bfloat16* __restrict__ Bl,
    const float* __restrict__ bias, float* __restrict__ C)
{
    extern __shared__ char smem[];
    const int N = DPROJ, K = DIN;
    int tid = threadIdx.x, lane = tid & 31, warp = tid >> 5;
    int rowBase = blockIdx.y * 128, colBase = blockIdx.x * 128;
    int warp_m = (warp >> 1) * 32, warp_n = (warp & 1) * 64;

    uint32_t sA = smem_addr_u32(smem);
    uint32_t sAhi = sA + SM_AHI, sAlo = sA + SM_ALO;
    uint32_t sBhi = sA + SM_BHI, sBlo = sA + SM_BLO;

    int q = lane >> 3, r = lane & 7;
    int a_row[2];
    a_row[0] = warp_m + (q & 1) * 8 + r;
    a_row[1] = a_row[0] + 16;
    int a_col = (q >> 1) * 8;
    int b_k = (q & 1) * 8 + r;
    int b_n[4];
#pragma unroll
    for (int p = 0; p < 4; p++) b_n[p] = warp_n + p * 16 + (q >> 1) * 8;

    int a_ch0 = tid, a_ch1 = tid + 256;
    int ar0 = a_ch0 >> 2, as0 = a_ch0 & 3, ar1 = a_ch1 >> 2, as1 = a_ch1 & 3;
    int bk0 = a_ch0 >> 4, bs0 = a_ch0 & 15, bk1 = a_ch1 >> 4, bs1 = a_ch1 & 15;

    const __nv_bfloat16* Ahp0 = Ah + (size_t)(rowBase + ar0) * K + as0 * 8;
    const __nv_bfloat16* Ahp1 = Ah + (size_t)(rowBase + ar1) * K + as1 * 8;
    const __nv_bfloat16* Alp0 = Al + (size_t)(rowBase + ar0) * K + as0 * 8;
    const __nv_bfloat16* Alp1 = Al + (size_t)(rowBase + ar1) * K + as1 * 8;
    const __nv_bfloat16* Bhp0 = Bh + (size_t)bk0 * N + colBase + bs0 * 8;
    const __nv_bfloat16* Bhp1 = Bh + (size_t)bk1 * N + colBase + bs1 * 8;
    const __nv_bfloat16* Blp0 = Bl + (size_t)bk0 * N + colBase + bs0 * 8;
    const __nv_bfloat16* Blp1 = Bl + (size_t)bk1 * N + colBase + bs1 * 8;

    float acc[2][8][4];
#pragma unroll
    for (int i = 0; i < 2; i++)
#pragma unroll
        for (int j = 0; j < 8; j++)
#pragma unroll
            for (int v = 0; v < 4; v++) acc[i][j][v] = 0.0f;

    uint4 pah0, pah1, pal0, pal1, pbh0, pbh1, pbl0, pbl1;
    pah0 = *(const uint4*)(Ahp0); pah1 = *(const uint4*)(Ahp1);
    pal0 = *(const uint4*)(Alp0); pal1 = *(const uint4*)(Alp1);
    pbh0 = *(const uint4*)(Bhp0); pbh1 = *(const uint4*)(Bhp1);
    pbl0 = *(const uint4*)(Blp0); pbl1 = *(const uint4*)(Blp1);
    {
        char* base = (char*)smem;
        *(uint4*)(base + SM_AHI + (ar0 * APITCH + as0 * 8) * 2) = pah0;
        *(uint4*)(base + SM_AHI + (ar1 * APITCH + as1 * 8) * 2) = pah1;
        *(uint4*)(base + SM_ALO + (ar0 * APITCH + as0 * 8) * 2) = pal0;
        *(uint4*)(base + SM_ALO + (ar1 * APITCH + as1 * 8) * 2) = pal1;
        *(uint4*)(base + SM_BHI + (bk0 * BPITCH + bs0 * 8) * 2) = pbh0;
        *(uint4*)(base + SM_BHI + (bk1 * BPITCH + bs1 * 8) * 2) = pbh1;
        *(uint4*)(base + SM_BLO + (bk0 * BPITCH + bs0 * 8) * 2) = pbl0;
        *(uint4*)(base + SM_BLO + (bk1 * BPITCH + bs1 * 8) * 2) = pbl1;
    }
    __syncthreads();

    const int nTiles = K / 32;
    int buf = 0;
    for (int kt = 0; kt < nTiles; kt++) {
        bool nxt = (kt + 1 < nTiles);
        if (nxt) {
            int ko = (kt + 1) * 32;
            pah0 = *(const uint4*)(Ahp0 + ko); pah1 = *(const uint4*)(Ahp1 + ko);
            pal0 = *(const uint4*)(Alp0 + ko); pal1 = *(const uint4*)(Alp1 + ko);
            pbh0 = *(const uint4*)(Bhp0 + (size_t)ko * N);
            pbh1 = *(const uint4*)(Bhp1 + (size_t)ko * N);
            pbl0 = *(const uint4*)(Blp0 + (size_t)ko * N);
            pbl1 = *(const uint4*)(Blp1 + (size_t)ko * N);
        }

#pragma unroll
        for (int ks = 0; ks < 2; ks++) {
            uint32_t aoffh = sAhi + ((buf * 128) * APITCH + ks * 16 + a_col) * 2;
            uint32_t aoffl = sAlo + ((buf * 128) * APITCH + ks * 16 + a_col) * 2;
            uint32_t ahi[2][4], alo[2][4];
#pragma unroll
            for (int i = 0; i < 2; i++) {
                uint32_t aa = aoffh + a_row[i] * (APITCH * 2);
                ldsm_x4(ahi[i][0], ahi[i][1], ahi[i][2], ahi[i][3], aa);
                uint32_t al2 = aoffl + a_row[i] * (APITCH * 2);
                ldsm_x4(alo[i][0], alo[i][1], alo[i][2], alo[i][3], al2);
            }
            uint32_t bhi[4][4], blo[4][4];
            uint32_t bkrow = (buf * 32 + ks * 16 + b_k) * (BPITCH * 2);
#pragma unroll
            for (int p = 0; p < 4; p++) {
                uint32_t ba = sBhi + bkrow + b_n[p] * 2;
                ldsm_x4_t(bhi[p][0], bhi[p][1], bhi[p][2], bhi[p][3], ba);
                uint32_t bb = sBlo + bkrow + b_n[p] * 2;
                ldsm_x4_t(blo[p][0], blo[p][1], blo[p][2], blo[p][3], bb);
            }
#pragma unroll
            for (int i = 0; i < 2; i++) {
#pragma unroll
                for (int p = 0; p < 4; p++) {
#pragma unroll
                    for (int t = 0; t < 2; t++) {
                        int j = p * 2 + t;
                        uint32_t b0h = bhi[p][t * 2], b1h = bhi[p][t * 2 + 1];
                        uint32_t b0l = blo[p][t * 2], b1l = blo[p][t * 2 + 1];
                        mma_bf16(acc[i][j], ahi[i], b0h, b1h);
                        mma_bf16(acc[i][j], ahi[i], b0l, b1l);
                        mma_bf16(acc[i][j], alo[i], b0h, b1h);
                    }
                }
            }
        }

        if (nxt) {
            int nb = buf ^ 1;
            char* base = (char*)smem;
            *(uint4*)(base + SM_AHI + ((nb * 128 + ar0) * APITCH + as0 * 8) * 2) = pah0;
            *(uint4*)(base + SM_AHI + ((nb * 128 + ar1) * APITCH + as1 * 8) * 2) = pah1;
            *(uint4*)(base + SM_ALO + ((nb * 128 + ar0) * APITCH + as0 * 8) * 2) = pal0;
            *(uint4*)(base + SM_ALO + ((nb * 128 + ar1) * APITCH + as1 * 8) * 2) = pal1;
            *(uint4*)(base + SM_BHI + ((nb * 32 + bk0) * BPITCH + bs0 * 8) * 2) = pbh0;
            *(uint4*)(base + SM_BHI + ((nb * 32 + bk1) * BPITCH + bs1 * 8) * 2) = pbh1;
            *(uint4*)(base + SM_BLO + ((nb * 32 + bk0) * BPITCH + bs0 * 8) * 2) = pbl0;
            *(uint4*)(base + SM_BLO + ((nb * 32 + bk1) * BPITCH + bs1 * 8) * 2) = pbl1;
        }
        __syncthreads();
        buf ^= 1;
    }

    int g = lane >> 2, tig = lane & 3;
#pragma unroll
    for (int i = 0; i < 2; i++) {
#pragma unroll
        for (int j = 0; j < 8; j++) {
            int col = colBase + warp_n + j * 8 + tig * 2;
            float2 bv = *(const float2*)(bias + col);
            int r0 = rowBase + warp_m + i * 16 + g;
            float2 o0 = make_float2(acc[i][j][0] + bv.x, acc[i][j][1] + bv.y);
            float2 o1 = make_float2(acc[i][j][2] + bv.x, acc[i][j][3] + bv.y);
            *(float2*)(C + (size_t)r0 * N + col) = o0;
            *(float2*)(C + (size_t)(r0 + 8) * N + col) = o1;
        }
    }
}

// ---------------------------------------------------------------------------
// SGEMM (fp32): scores / PV / G*.  Unchanged.
// ---------------------------------------------------------------------------
__global__ void __launch_bounds__(256, 2) sgemm128(
    const float* __restrict__ A, const float* __restrict__ B,
    const float* __restrict__ bias, float* __restrict__ C,
    int M, int N, int K,
    size_t sA, size_t sB, size_t sC,
    int transB, int mode)
{
    constexpr int BM = 128, BN = 128, BK = 16, PAD = 4;
    __shared__ float As[2][BK][BM + PAD];
    __shared__ float Bs[2][BK][BN + PAD];

    int bx = blockIdx.x, by = blockIdx.y, bz = blockIdx.z;
    int rowBase = by * BM, colBase = bx * BN;
    if (mode == 1 && rowBase + BM - 1 < colBase) return;
    int Kend = K;
    if (mode == 2) Kend = (rowBase + BM < K) ? rowBase + BM : K;

    const float* Ab = A + sA * (size_t)bz;
    const float* Bb = B + sB * (size_t)bz;
    float*       Cb = C + sC * (size_t)bz;

    int tid = threadIdx.x;
    int ty = tid >> 4, tx = tid & 15;
    int row0 = ty * 8;
    int c0 = tx * 4, c1 = 64 + tx * 4;

    int arow = tid >> 1, akof = (tid & 1) * 8;
    const float* aptr = Ab + (size_t)(rowBase + arow) * K + akof;

    int bkr = tid >> 4, bnc = (tid & 15) * 8;
    int bnr = tid >> 1, bkof = (tid & 1) * 8;
    const float* bptr = transB
        ? Bb + (size_t)(colBase + bnr) * K + bkof
        : Bb + (size_t)bkr * N + colBase + bnc;

    float acc[8][8];
#pragma unroll
    for (int i = 0; i < 8; i++)
#pragma unroll
        for (int j = 0; j < 8; j++) acc[i][j] = 0.0f;

    int nTiles = Kend / BK;

    {
        float4 a0 = *(const float4*)(aptr);
        float4 a1 = *(const float4*)(aptr + 4);
        As[0][akof + 0][arow] = a0.x; As[0][akof + 1][arow] = a0.y;
        As[0][akof + 2][arow] = a0.z; As[0][akof + 3][arow] = a0.w;
        As[0][akof + 4][arow] = a1.x; As[0][akof + 5][arow] = a1.y;
        As[0][akof + 6][arow] = a1.z; As[0][akof + 7][arow] = a1.w;
        float4 b0 = *(const float4*)(bptr);
        float4 b1 = *(const float4*)(bptr + 4);
        if (!transB) {
            *(float4*)&Bs[0][bkr][bnc]     = b0;
            *(float4*)&Bs[0][bkr][bnc + 4] = b1;
        } else {
            Bs[0][bkof + 0][bnr] = b0.x; Bs[0][bkof + 1][bnr] = b0.y;
            Bs[0][bkof + 2][bnr] = b0.z; Bs[0][bkof + 3][bnr] = b0.w;
            Bs[0][bkof + 4][bnr] = b1.x; Bs[0][bkof + 5][bnr] = b1.y;
            Bs[0][bkof + 6][bnr] = b1.z; Bs[0][bkof + 7][bnr] = b1.w;
        }
    }
    __syncthreads();

    int buf = 0;
    for (int t0 = 0; t0 < nTiles; t0++) {
        float4 na0, na1, nb0, nb1;
        bool nxt = (t0 + 1 < nTiles);
        if (nxt) {
            const float* ap = aptr + (t0 + 1) * BK;
            na0 = *(const float4*)(ap);
            na1 = *(const float4*)(ap + 4);
            const float* bp = transB ? bptr + (t0 + 1) * BK
                                     : bptr + (size_t)(t0 + 1) * BK * N;
            nb0 = *(const float4*)(bp);
            nb1 = *(const float4*)(bp + 4);
        }

        float4 fa0 = *(const float4*)&As[buf][0][row0];
        float4 fa1 = *(const float4*)&As[buf][0][row0 + 4];
        float4 fb0 = *(const float4*)&Bs[buf][0][c0];
        float4 fb1 = *(const float4*)&Bs[buf][0][c1];
#pragma unroll
        for (int kk = 0; kk < BK; kk++) {
            float4 ga0, ga1, gb0, gb1;
            if (kk < BK - 1) {
                ga0 = *(const float4*)&As[buf][kk + 1][row0];
                ga1 = *(const float4*)&As[buf][kk + 1][row0 + 4];
                gb0 = *(const float4*)&Bs[buf][kk + 1][c0];
                gb1 = *(const float4*)&Bs[buf][kk + 1][c1];
            }
            float a[8] = {fa0.x, fa0.y, fa0.z, fa0.w, fa1.x, fa1.y, fa1.z, fa1.w};
            float b[8] = {fb0.x, fb0.y, fb0.z, fb0.w, fb1.x, fb1.y, fb1.z, fb1.w};
#pragma unroll
            for (int i = 0; i < 8; i++)
#pragma unroll
                for (int j = 0; j < 8; j++)
                    acc[i][j] = fmaf(a[i], b[j], acc[i][j]);
            if (kk < BK - 1) { fa0 = ga0; fa1 = ga1; fb0 = gb0; fb1 = gb1; }
        }

        if (nxt) {
            int nb = buf ^ 1;
            As[nb][akof + 0][arow] = na0.x; As[nb][akof + 1][arow] = na0.y;
            As[nb][akof + 2][arow] = na0.z; As[nb][akof + 3][arow] = na0.w;
            As[nb][akof + 4][arow] = na1.x; As[nb][akof + 5][arow] = na1.y;
            As[nb][akof + 6][arow] = na1.z; As[nb][akof + 7][arow] = na1.w;
            if (!transB) {
                *(float4*)&Bs[nb][bkr][bnc]     = nb0;
                *(float4*)&Bs[nb][bkr][bnc + 4] = nb1;
            } else {
                Bs[nb][bkof + 0][bnr] = nb0.x; Bs[nb][bkof + 1][bnr] = nb0.y;
                Bs[nb][bkof + 2][bnr] = nb0.z; Bs[nb][bkof + 3][bnr] = nb0.w;
                Bs[nb][bkof + 4][bnr] = nb1.x; Bs[nb][bkof + 5][bnr] = nb1.y;
                Bs[nb][bkof + 6][bnr] = nb1.z; Bs[nb][bkof + 7][bnr] = nb1.w;
            }
        }
        __syncthreads();
        buf ^= 1;
    }

    float4 bv0 = make_float4(0.f, 0.f, 0.f, 0.f);
    float4 bv1 = bv0;
    if (bias) {
        bv0 = *(const float4*)(bias + colBase + c0);
        bv1 = *(const float4*)(bias + colBase + c1);
    }
#pragma unroll
    for (int i = 0; i < 8; i++) {
        size_t row = (size_t)(rowBase + row0 + i);
        float4 o0 = make_float4(acc[i][0] + bv0.x, acc[i][1] + bv0.y,
                                acc[i][2] + bv0.z, acc[i][3] + bv0.w);
        float4 o1 = make_float4(acc[i][4] + bv1.x, acc[i][5] + bv1.y,
                                acc[i][6] + bv1.z, acc[i][7] + bv1.w);
        *(float4*)(Cb + row * N + colBase + c0) = o0;
        *(float4*)(Cb + row * N + colBase + c1) = o1;
    }
}

// ---------------------------------------------------------------------------
// Causal row softmax, in place.
// ---------------------------------------------------------------------------
__global__ void softmax_causal_kernel()
{
    int r = blockIdx.x, b = blockIdx.y;
    float* row = g_S + ((size_t)b * SEQ + r) * SEQ;
    int len = r + 1;
    int tid = threadIdx.x;
    __shared__ float buf[SEQ];
    __shared__ float red[256];
    const float inv = rsqrtf(512.0f);

    float m = -3.4e38f;
    for (int i = tid; i < len; i += 256) m = fmaxf(m, row[i]);
    red[tid] = m; __syncthreads();
    for (int s = 128; s; s >>= 1) { if (tid < s) red[tid] = fmaxf(red[tid], red[tid + s]); __syncthreads(); }
    m = red[0] * inv;
    __syncthreads();

    float ssum = 0.0f;
    for (int i = tid; i < len; i += 256) {
        float e = __expf(row[i] * inv - m);
        buf[i] = e;
        ssum += e;
    }
    red[tid] = ssum; __syncthreads();
    for (int s = 128; s; s >>= 1) { if (tid < s) red[tid] += red[tid + s]; __syncthreads(); }
    float denom = 1.0f / red[0];
    __syncthreads();

    for (int i = tid; i < SEQ; i += 256)
        row[i] = (i < len) ? buf[i] * denom : 0.0f;
}

// ---------------------------------------------------------------------------
// Prefix pooling + h0.
// ---------------------------------------------------------------------------
__global__ void pool_kernel(const float* __restrict__ Wscore,
                            const float* __restrict__ Wp2h,
                            const float* __restrict__ bp2h)
{
    int b = blockIdx.x;
    const float* feat = g_feat + (size_t)b * SEQ * DPROJ;
    __shared__ float wsc[512];
    __shared__ float sc[512];
    __shared__ float pooled[512];
    __shared__ float red[256];
    int tid = threadIdx.x;

    for (int i = tid; i < 512; i += 256) wsc[i] = Wscore[i];
    __syncthreads();

    int w = tid >> 5, l = tid & 31;
    for (int u = w; u < ASSIST; u += 8) {
        float s = 0.0f;
        for (int p = l; p < DPROJ; p += 32)
            s = fmaf(feat[(size_t)u * DPROJ + p], wsc[p], s);
#pragma unroll
        for (int o = 16; o; o >>= 1) s += __shfl_xor_sync(0xffffffffu, s, o);
        if (l == 0) sc[u] = s;
    }
    __syncthreads();

    float m = fmaxf(sc[tid], sc[tid + 256]);
    red[tid] = m; __syncthreads();
    for (int s = 128; s; s >>= 1) { if (tid < s) red[tid] = fmaxf(red[tid], red[tid + s]); __syncthreads(); }
    m = red[0]; __syncthreads();

    float e0 = expf(sc[tid] - m), e1 = expf(sc[tid + 256] - m);
    red[tid] = e0 + e1; __syncthreads();
    for (int s = 128; s; s >>= 1) { if (tid < s) red[tid] += red[tid + s]; __syncthreads(); }
    float inv = 1.0f / red[0];
    __syncthreads();
    sc[tid] = e0 * inv; sc[tid + 256] = e1 * inv;
    __syncthreads();

    for (int p = tid; p < DPROJ; p += 256) {
        float acc = 0.0f;
        for (int u = 0; u < ASSIST; u++)
            acc = fmaf(sc[u], feat[(size_t)u * DPROJ + p], acc);
        pooled[p] = acc;
    }
    __syncthreads();

    for (int c = tid; c < DMEM; c += 256) {
        float acc = bp2h[c];
        for (int k = 0; k < DPROJ; k++)
            acc = fmaf(pooled[k], Wp2h[(size_t)k * DMEM + c], acc);
        g_h[b * DMEM + c] = tanhf(acc);
    }
}

__global__ void init_out_kernel(float* __restrict__ out, const float* __restrict__ bmem)
{
    int i = blockIdx.x * blockDim.x + threadIdx.x;
    if (i < BATCH * RUN) out[i] = bmem[0];
}

// ---------------------------------------------------------------------------
// Cluster scan — R11 skeleton (2 cluster.syncs/step, DSMEM broadcast, all U
// in registers) but with WARP-INTERNAL reductions: 16 warps x 2 columns;
// lane = (sub = l>>4 -> column, ks = l&15 -> 32-k slice).  Partial dots
// reduce via 4 shfl_xor (1,2,4,8) inside the 16-lane half-warp; lane ks==0
// is the producer (sigmoid/tanh, DSMEM broadcast).  No part[] smem, no
// reduction __syncthreads.  Logit via fire-and-forget global RED.ADD.
// ---------------------------------------------------------------------------
#define SCAN_THREADS 512
#define CL 16

#define H_OFF    0                 // float[512]   2048
#define RH_OFF   2048              // float[512]   2048
#define SCAN_SMEM 4096

__device__ __forceinline__ uint32_t mapa_rank(uint32_t saddr, uint32_t rank) {
    uint32_t r;
    asm("mapa.shared::cluster.u32 %0, %1, %2;" : "=r"(r) : "r"(saddr), "r"(rank));
    return r;
}
__device__ __forceinline__ void stc_f32(uint32_t addr, float v) {
    asm volatile("st.shared::cluster.f32 [%0], %1;" :: "r"(addr), "f"(v));
}
#define CLUSTER_SYNC() do { \
    asm volatile("barrier.cluster.arrive.aligned;" ::: "memory"); \
    asm volatile("barrier.cluster.wait.aligned;" ::: "memory"); \
} while (0)

__global__ void __launch_bounds__(SCAN_THREADS, 1) scan_cluster(
    const float* __restrict__ Uz, const float* __restrict__ Ur,
    const float* __restrict__ Uh, const float* __restrict__ Wmem,
    const float* __restrict__ Gz, const float* __restrict__ Gr,
    const float* __restrict__ Gh, float* __restrict__ out)
{
    extern __shared__ char smem[];
    float* h_s  = (float*)(smem + H_OFF);
    float* rh_s = (float*)(smem + RH_OFF);

    int tid = threadIdx.x;
    int w   = tid >> 5;            // warp 0..15
    int l   = tid & 31;
    int sub = l >> 4;              // 0/1 -> which of the warp's 2 columns
    int ks  = l & 15;              // 16 k-segments of 32
    int kbase = ks * 32;
    int colLocal = 2 * w + sub;    // 0..31

    uint32_t rank;
    asm("mov.u32 %0, %%cluster_ctarank;" : "=r"(rank));
    int cg0 = (int)rank * 32;
    int col = cg0 + colLocal;      // global state column this thread serves
    int gb  = blockIdx.x >> 4;     // batch = cluster id

    // register-resident U slices (column col, k in [kbase, kbase+32))
    float uz[32], ur[32], uh[32];
#pragma unroll
    for (int i = 0; i < 32; i++) {
        uz[i] = Uz[(size_t)(kbase + i) * DMEM + col];
        ur[i] = Ur[(size_t)(kbase + i) * DMEM + col];
        uh[i] = Uh[(size_t)(kbase + i) * DMEM + col];
    }
    bool isRed = (ks == 0);
    float wm = isRed ? Wmem[col] : 0.0f;

    h_s[tid] = __ldcg(&g_h[(size_t)gb * DMEM + tid]);
    __syncthreads();
    CLUSTER_SYNC();

    uint32_t rh_base = smem_addr_u32(rh_s);
    uint32_t h_base  = smem_addr_u32(h_s);

    const float dtc = 1.0f / 1535.0f;

    for (int t = 0; t < RUN; t++) {
        float dtv = (t == 0) ? 0.0f : dtc;

        float gz = 0.0f, gr = 0.0f, gh2 = 0.0f;
        if (isRed) {
            size_t off = ((size_t)(gb * RUN + t)) * DMEM + col;
            gz  = __ldg(&Gz[off]);
            gr  = __ldg(&Gr[off]);
            gh2 = __ldg(&Gh[off]);
        }

        // ---- phase A: z/r partial dots over this thread's 32-k slice ----
        float pz = 0.f, pr = 0.f;
        const float4* hp = (const float4*)&h_s[kbase];
#pragma unroll
        for (int i = 0; i < 8; i++) {
            float4 h4 = hp[i];
            pz = fmaf(h4.x, uz[4*i+0], pz); pr = fmaf(h4.x, ur[4*i+0], pr);
            pz = fmaf(h4.y, uz[4*i+1], pz); pr = fmaf(h4.y, ur[4*i+1], pr);
            pz = fmaf(h4.z, uz[4*i+2], pz); pr = fmaf(h4.z, ur[4*i+2], pr);
            pz = fmaf(h4.w, uz[4*i+3], pz); pr = fmaf(h4.w, ur[4*i+3], pr);
        }
        // reduce within the 16-lane half-warp (same column)
#pragma unroll
        for (int o = 1; o < 16; o <<= 1) {
            pz += __shfl_xor_sync(0xffffffffu, pz, o);
            pr += __shfl_xor_sync(0xffffffffu, pr, o);
        }

        float zreg = 0.0f;
        if (isRed) {
            zreg = 1.0f / (1.0f + __expf(-(gz + pz)));
            float rr = 1.0f / (1.0f + __expf(-(gr + pr)));
            float rhv = rr * h_s[col];
            uint32_t a = rh_base + (uint32_t)col * 4u;
#pragma unroll
            for (int rk = 0; rk < CL; rk++)
                stc_f32(mapa_rank(a, (uint32_t)rk), rhv);
        }
        CLUSTER_SYNC();

        // ---- phase B: candidate partial dots ----
        float ph = 0.f;
        const float4* rp = (const float4*)&rh_s[kbase];
#pragma unroll
        for (int i = 0; i < 8; i++) {
            float4 r4 = rp[i];
            ph = fmaf(r4.x, uh[4*i+0], ph);
            ph = fmaf(r4.y, uh[4*i+1], ph);
            ph = fmaf(r4.z, uh[4*i+2], ph);
            ph = fmaf(r4.w, uh[4*i+3], ph);
        }
#pragma unroll
        for (int o = 1; o < 16; o <<= 1)
            ph += __shfl_xor_sync(0xffffffffu, ph, o);

        if (isRed) {
            float hh   = tanhf(gh2 + ph);
            float hold = h_s[col];
            float hnew = hold + zreg * (hh - hold);
            float hout = hnew + dtv * (hnew - hold);
            if (t < RUN - 1) {
                uint32_t a = h_base + (uint32_t)col * 4u;
#pragma unroll
                for (int rk = 0; rk < CL; rk++)
                    stc_f32(mapa_rank(a, (uint32_t)rk), hout);
            }
            // fire-and-forget logit contribution (RED.ADD, off critical path)
            atomicAdd(&out[gb * RUN + t], hout * wm);
        }
        CLUSTER_SYNC();
    }
}

// ---------------------------------------------------------------------------
// Host
// ---------------------------------------------------------------------------
extern "C" void kernel_launch(void* const* d_in, const int* in_sizes, int n_in,
                              void* d_out, int out_size)
{
    const float* x      = (const float*)d_in[0];
    const float* Wq     = (const float*)d_in[1];
    const float* bq     = (const float*)d_in[2];
    const float* Wk     = (const float*)d_in[3];
    const float* bk     = (const float*)d_in[4];
    const float* Wv     = (const float*)d_in[5];
    const float* bv     = (const float*)d_in[6];
    const float* Wz     = (const float*)d_in[7];
    const float* Uz     = (const float*)d_in[8];
    const float* bz     = (const float*)d_in[9];
    const float* Wr     = (const float*)d_in[10];
    const float* Ur     = (const float*)d_in[11];
    const float* br     = (const float*)d_in[12];
    const float* Wh     = (const float*)d_in[13];
    const float* Uh     = (const float*)d_in[14];
    const float* bh     = (const float*)d_in[15];
    const float* Wmem   = (const float*)d_in[16];
    const float* bmem   = (const float*)d_in[17];
    const float* Wp2h   = (const float*)d_in[18];
    const float* bp2h   = (const float*)d_in[19];
    const float* Wscore = (const float*)d_in[20];
    (void)in_sizes; (void)n_in;
    float* out = (float*)d_out;

    float *pQ, *pK, *pV, *pS, *pF, *pGz, *pGr, *pGh;
    cudaGetSymbolAddress((void**)&pQ,  g_Q);
    cudaGetSymbolAddress((void**)&pK,  g_K);
    cudaGetSymbolAddress((void**)&pV,  g_V);
    cudaGetSymbolAddress((void**)&pS,  g_S);
    cudaGetSymbolAddress((void**)&pF,  g_feat);
    cudaGetSymbolAddress((void**)&pGz, g_Gz);
    cudaGetSymbolAddress((void**)&pGr, g_Gr);
    cudaGetSymbolAddress((void**)&pGh, g_Gh);

    __nv_bfloat16 *pxh, *pxl, *pWh, *pWl;
    cudaGetSymbolAddress((void**)&pxh, g_xhi);
    cudaGetSymbolAddress((void**)&pxl, g_xlo);
    cudaGetSymbolAddress((void**)&pWh, g_Whi);
    cudaGetSymbolAddress((void**)&pWl, g_Wlo);

    dim3 t256(256);
    const size_t WSZ = (size_t)DIN * DPROJ;

    // split x and W into bf16 (hi, lo)
    split_kernel<<<2048, t256>>>(x,  pxh, pxl, (size_t)ROWS * DIN / 4);
    split_kernel<<<512,  t256>>>(Wq, pWh,           pWl,           WSZ / 4);
    split_kernel<<<512,  t256>>>(Wk, pWh + WSZ,     pWl + WSZ,     WSZ / 4);
    split_kernel<<<512,  t256>>>(Wv, pWh + 2 * WSZ, pWl + 2 * WSZ, WSZ / 4);

    // tensor-core QKV projections
    cudaFuncSetAttribute(qkv_mma_kernel,
                         cudaFuncAttributeMaxDynamicSharedMemorySize, QKV_SMEM);
    {
        dim3 g(DPROJ / 128, ROWS / 128, 1);
        qkv_mma_kernel<<<g, t256, QKV_SMEM>>>(pxh, pxl, pWh,           pWl,           bq, pQ);
        qkv_mma_kernel<<<g, t256, QKV_SMEM>>>(pxh, pxl, pWh + WSZ,     pWl + WSZ,     bk, pK);
        qkv_mma_kernel<<<g, t256, QKV_SMEM>>>(pxh, pxl, pWh + 2 * WSZ, pWl + 2 * WSZ, bv, pV);
    }

    // scores = Q K^T (causal tile skip)
    {
        dim3 g(SEQ / 128, SEQ / 128, BATCH);
        sgemm128<<<g, t256>>>(pQ, pK, nullptr, pS, SEQ, SEQ, DPROJ,
                              (size_t)SEQ * DPROJ, (size_t)SEQ * DPROJ,
                              (size_t)SEQ * SEQ, 1, 1);
    }

    softmax_causal_kernel<<<dim3(SEQ, BATCH), t256>>>();

    // feat = P V (K-limited: P lower-triangular)
    {
        dim3 g(DPROJ / 128, SEQ / 128, BATCH);
        sgemm128<<<g, t256>>>(pS, pV, nullptr, pF, SEQ, DPROJ, SEQ,
                              (size_t)SEQ * SEQ, (size_t)SEQ * DPROJ,
                              (size_t)SEQ * DPROJ, 0, 2);
    }

    pool_kernel<<<BATCH, t256>>>(Wscore, Wp2h, bp2h);

    // G* = feat_assist @ W* + b*
    {
        dim3 g(DMEM / 128, RUN / 128, BATCH);
        const float* Aoff = pF + (size_t)ASSIST * DPROJ;
        sgemm128<<<g, t256>>>(Aoff, Wz, bz, pGz, RUN, DMEM, DPROJ,
                              (size_t)SEQ * DPROJ, 0, (size_t)RUN * DMEM, 0, 0);
        sgemm128<<<g, t256>>>(Aoff, Wr, br, pGr, RUN, DMEM, DPROJ,
                              (size_t)SEQ * DPROJ, 0, (size_t)RUN * DMEM, 0, 0);
        sgemm128<<<g, t256>>>(Aoff, Wh, bh, pGh, RUN, DMEM, DPROJ,
                              (size_t)SEQ * DPROJ, 0, (size_t)RUN * DMEM, 0, 0);
    }

    init_out_kernel<<<(BATCH * RUN + 255) / 256, t256>>>(out, bmem);

    // cluster scan: 4 clusters x 16 CTAs x 512 threads (1 batch / cluster)
    cudaFuncSetAttribute(scan_cluster,
                         cudaFuncAttributeMaxDynamicSharedMemorySize, SCAN_SMEM);
    cudaFuncSetAttribute(scan_cluster,
                         cudaFuncAttributeNonPortableClusterSizeAllowed, 1);
    {
        cudaLaunchConfig_t cfg = {};
        cfg.gridDim  = dim3(64, 1, 1);
        cfg.blockDim = dim3(SCAN_THREADS, 1, 1);
        cfg.dynamicSmemBytes = SCAN_SMEM;
        cfg.stream = 0;
        cudaLaunchAttribute attrs[1];
        attrs[0].id = cudaLaunchAttributeClusterDimension;
        attrs[0].val.clusterDim.x = CL;
        attrs[0].val.clusterDim.y = 1;
        attrs[0].val.clusterDim.z = 1;
        cfg.attrs = attrs;
        cfg.numAttrs = 1;
        cudaLaunchKernelEx(&cfg, scan_cluster,
                           Uz, Ur, Uh, Wmem,
                           (const float*)pGz, (const float*)pGr,
                           (const float*)pGh, out);
    }

    (void)out_size;
}

// round 14
// speedup vs baseline: 2.4104x; 2.4104x over previous
#include <cuda_runtime.h>
#include <cuda_bf16.h>
#include <math.h>
#include <stdint.h>

// ---------------------------------------------------------------------------
// Problem constants
// ---------------------------------------------------------------------------
#define BATCH   4
#define SEQ     2048
#define DIN     4096
#define DPROJ   512
#define DMEM    512
#define ASSIST  512
#define RUN     1536
#define ROWS    (BATCH*SEQ)   // 8192

// ---------------------------------------------------------------------------
// Device scratch
// ---------------------------------------------------------------------------
__device__ float g_Q[(size_t)ROWS*DPROJ];
__device__ float g_K[(size_t)ROWS*DPROJ];
__device__ float g_V[(size_t)ROWS*DPROJ];
__device__ float g_S[(size_t)BATCH*SEQ*SEQ];
__device__ float g_feat[(size_t)ROWS*DPROJ];
__device__ float g_Gz[(size_t)BATCH*RUN*DMEM];
__device__ float g_Gr[(size_t)BATCH*RUN*DMEM];
__device__ float g_Gh[(size_t)BATCH*RUN*DMEM];
__device__ float g_h[BATCH*DMEM];

// bf16 split operands (g_xhi/g_xlo reused for Q/K splits after QKV)
__device__ __nv_bfloat16 g_xhi[(size_t)ROWS*DIN];
__device__ __nv_bfloat16 g_xlo[(size_t)ROWS*DIN];
__device__ __nv_bfloat16 g_Whi[3][(size_t)DIN*DPROJ];
__device__ __nv_bfloat16 g_Wlo[3][(size_t)DIN*DPROJ];

// ---------------------------------------------------------------------------
// Split fp32 -> (hi, lo) bf16.
// ---------------------------------------------------------------------------
__global__ void split_kernel(const float* __restrict__ src,
                             __nv_bfloat16* __restrict__ hi,
                             __nv_bfloat16* __restrict__ lo, size_t n4)
{
    size_t i = (size_t)blockIdx.x * blockDim.x + threadIdx.x;
    size_t stride = (size_t)gridDim.x * blockDim.x;
    for (; i < n4; i += stride) {
        float4 v = ((const float4*)src)[i];
        __nv_bfloat16 h0 = __float2bfloat16(v.x);
        __nv_bfloat16 h1 = __float2bfloat16(v.y);
        __nv_bfloat16 h2 = __float2bfloat16(v.z);
        __nv_bfloat16 h3 = __float2bfloat16(v.w);
        __nv_bfloat162 hh0 = {h0, h1}, hh1 = {h2, h3};
        __nv_bfloat162 ll0 = {__float2bfloat16(v.x - __bfloat162float(h0)),
                              __float2bfloat16(v.y - __bfloat162float(h1))};
        __nv_bfloat162 ll1 = {__float2bfloat16(v.z - __bfloat162float(h2)),
                              __float2bfloat16(v.w - __bfloat162float(h3))};
        ((__nv_bfloat162*)hi)[i * 2]     = hh0;
        ((__nv_bfloat162*)hi)[i * 2 + 1] = hh1;
        ((__nv_bfloat162*)lo)[i * 2]     = ll0;
        ((__nv_bfloat162*)lo)[i * 2 + 1] = ll1;
    }
}

// ---------------------------------------------------------------------------
// MMA helpers
// ---------------------------------------------------------------------------
__device__ __forceinline__ uint32_t smem_addr_u32(const void* p) {
    uint32_t a;
    asm("{ .reg .u64 t; cvta.to.shared.u64 t, %1; cvt.u32.u64 %0, t; }"
        : "=r"(a) : "l"(p));
    return a;
}
__device__ __forceinline__ void ldsm_x4(uint32_t& r0, uint32_t& r1,
                                        uint32_t& r2, uint32_t& r3, uint32_t a) {
    asm volatile("ldmatrix.sync.aligned.m8n8.x4.shared.b16 {%0,%1,%2,%3}, [%4];"
                 : "=r"(r0), "=r"(r1), "=r"(r2), "=r"(r3) : "r"(a));
}
__device__ __forceinline__ void ldsm_x4_t(uint32_t& r0, uint32_t& r1,
                                          uint32_t& r2, uint32_t& r3, uint32_t a) {
    asm volatile("ldmatrix.sync.aligned.m8n8.x4.trans.shared.b16 {%0,%1,%2,%3}, [%4];"
                 : "=r"(r0), "=r"(r1), "=r"(r2), "=r"(r3) : "r"(a));
}
__device__ __forceinline__ void mma_bf16(float* d, const uint32_t* a,
                                         uint32_t b0, uint32_t b1) {
    asm volatile(
        "mma.sync.aligned.m16n8k16.row.col.f32.bf16.bf16.f32 "
        "{%0,%1,%2,%3}, {%4,%5,%6,%7}, {%8,%9}, {%0,%1,%2,%3};"
        : "+f"(d[0]), "+f"(d[1]), "+f"(d[2]), "+f"(d[3])
        : "r"(a[0]), "r"(a[1]), "r"(a[2]), "r"(a[3]), "r"(b0), "r"(b1));
}

// ---------------------------------------------------------------------------
// Tensor-core QKV GEMM (bf16x3) — unchanged (proven).
// ---------------------------------------------------------------------------
#define APITCH 40
#define BPITCH 136
#define SM_AHI 0
#define SM_ALO 20480
#define SM_BHI 40960
#define SM_BLO 58368
#define QKV_SMEM 75776

__global__ void __launch_bounds__(256) qkv_mma_kernel(
    const __nv_bfloat16* __restrict__ Ah, const __nv_bfloat16* __restrict__ Al,
    const __nv_bfloat16* __restrict__ Bh, const __nv_bfloat16* __restrict__ Bl,
    const float* __restrict__ bias, float* __restrict__ C)
{
    extern __shared__ char smem[];
    const int N = DPROJ, K = DIN;
    int tid = threadIdx.x, lane = tid & 31, warp = tid >> 5;
    int rowBase = blockIdx.y * 128, colBase = blockIdx.x * 128;
    int warp_m = (warp >> 1) * 32, warp_n = (warp & 1) * 64;

    uint32_t sA = smem_addr_u32(smem);
    uint32_t sAhi = sA + SM_AHI, sAlo = sA + SM_ALO;
    uint32_t sBhi = sA + SM_BHI, sBlo = sA + SM_BLO;

    int q = lane >> 3, r = lane & 7;
    int a_row[2];
    a_row[0] = warp_m + (q & 1) * 8 + r;
    a_row[1] = a_row[0] + 16;
    int a_col = (q >> 1) * 8;
    int b_k = (q & 1) * 8 + r;
    int b_n[4];
#pragma unroll
    for (int p = 0; p < 4; p++) b_n[p] = warp_n + p * 16 + (q >> 1) * 8;

    int a_ch0 = tid, a_ch1 = tid + 256;
    int ar0 = a_ch0 >> 2, as0 = a_ch0 & 3, ar1 = a_ch1 >> 2, as1 = a_ch1 & 3;
    int bk0 = a_ch0 >> 4, bs0 = a_ch0 & 15, bk1 = a_ch1 >> 4, bs1 = a_ch1 & 15;

    const __nv_bfloat16* Ahp0 = Ah + (size_t)(rowBase + ar0) * K + as0 * 8;
    const __nv_bfloat16* Ahp1 = Ah + (size_t)(rowBase + ar1) * K + as1 * 8;
    const __nv_bfloat16* Alp0 = Al + (size_t)(rowBase + ar0) * K + as0 * 8;
    const __nv_bfloat16* Alp1 = Al + (size_t)(rowBase + ar1) * K + as1 * 8;
    const __nv_bfloat16* Bhp0 = Bh + (size_t)bk0 * N + colBase + bs0 * 8;
    const __nv_bfloat16* Bhp1 = Bh + (size_t)bk1 * N + colBase + bs1 * 8;
    const __nv_bfloat16* Blp0 = Bl + (size_t)bk0 * N + colBase + bs0 * 8;
    const __nv_bfloat16* Blp1 = Bl + (size_t)bk1 * N + colBase + bs1 * 8;

    float acc[2][8][4];
#pragma unroll
    for (int i = 0; i < 2; i++)
#pragma unroll
        for (int j = 0; j < 8; j++)
#pragma unroll
            for (int v = 0; v < 4; v++) acc[i][j][v] = 0.0f;

    uint4 pah0, pah1, pal0, pal1, pbh0, pbh1, pbl0, pbl1;
    pah0 = *(const uint4*)(Ahp0); pah1 = *(const uint4*)(Ahp1);
    pal0 = *(const uint4*)(Alp0); pal1 = *(const uint4*)(Alp1);
    pbh0 = *(const uint4*)(Bhp0); pbh1 = *(const uint4*)(Bhp1);
    pbl0 = *(const uint4*)(Blp0); pbl1 = *(const uint4*)(Blp1);
    {
        char* base = (char*)smem;
        *(uint4*)(base + SM_AHI + (ar0 * APITCH + as0 * 8) * 2) = pah0;
        *(uint4*)(base + SM_AHI + (ar1 * APITCH + as1 * 8) * 2) = pah1;
        *(uint4*)(base + SM_ALO + (ar0 * APITCH + as0 * 8) * 2) = pal0;
        *(uint4*)(base + SM_ALO + (ar1 * APITCH + as1 * 8) * 2) = pal1;
        *(uint4*)(base + SM_BHI + (bk0 * BPITCH + bs0 * 8) * 2) = pbh0;
        *(uint4*)(base + SM_BHI + (bk1 * BPITCH + bs1 * 8) * 2) = pbh1;
        *(uint4*)(base + SM_BLO + (bk0 * BPITCH + bs0 * 8) * 2) = pbl0;
        *(uint4*)(base + SM_BLO + (bk1 * BPITCH + bs1 * 8) * 2) = pbl1;
    }
    __syncthreads();

    const int nTiles = K / 32;
    int buf = 0;
    for (int kt = 0; kt < nTiles; kt++) {
        bool nxt = (kt + 1 < nTiles);
        if (nxt) {
            int ko = (kt + 1) * 32;
            pah0 = *(const uint4*)(Ahp0 + ko); pah1 = *(const uint4*)(Ahp1 + ko);
            pal0 = *(const uint4*)(Alp0 + ko); pal1 = *(const uint4*)(Alp1 + ko);
            pbh0 = *(const uint4*)(Bhp0 + (size_t)ko * N);
            pbh1 = *(const uint4*)(Bhp1 + (size_t)ko * N);
            pbl0 = *(const uint4*)(Blp0 + (size_t)ko * N);
            pbl1 = *(const uint4*)(Blp1 + (size_t)ko * N);
        }

#pragma unroll
        for (int ks = 0; ks < 2; ks++) {
            uint32_t aoffh = sAhi + ((buf * 128) * APITCH + ks * 16 + a_col) * 2;
            uint32_t aoffl = sAlo + ((buf * 128) * APITCH + ks * 16 + a_col) * 2;
            uint32_t ahi[2][4], alo[2][4];
#pragma unroll
            for (int i = 0; i < 2; i++) {
                uint32_t aa = aoffh + a_row[i] * (APITCH * 2);
                ldsm_x4(ahi[i][0], ahi[i][1], ahi[i][2], ahi[i][3], aa);
                uint32_t al2 = aoffl + a_row[i] * (APITCH * 2);
                ldsm_x4(alo[i][0], alo[i][1], alo[i][2], alo[i][3], al2);
            }
            uint32_t bhi[4][4], blo[4][4];
            uint32_t bkrow = (buf * 32 + ks * 16 + b_k) * (BPITCH * 2);
#pragma unroll
            for (int p = 0; p < 4; p++) {
                uint32_t ba = sBhi + bkrow + b_n[p] * 2;
                ldsm_x4_t(bhi[p][0], bhi[p][1], bhi[p][2], bhi[p][3], ba);
                uint32_t bb = sBlo + bkrow + b_n[p] * 2;
                ldsm_x4_t(blo[p][0], blo[p][1], blo[p][2], blo[p][3], bb);
            }
#pragma unroll
            for (int i = 0; i < 2; i++) {
#pragma unroll
                for (int p = 0; p < 4; p++) {
#pragma unroll
                    for (int t = 0; t < 2; t++) {
                        int j = p * 2 + t;
                        uint32_t b0h = bhi[p][t * 2], b1h = bhi[p][t * 2 + 1];
                        uint32_t b0l = blo[p][t * 2], b1l = blo[p][t * 2 + 1];
                        mma_bf16(acc[i][j], ahi[i], b0h, b1h);
                        mma_bf16(acc[i][j], ahi[i], b0l, b1l);
                        mma_bf16(acc[i][j], alo[i], b0h, b1h);
                    }
                }
            }
        }

        if (nxt) {
            int nb = buf ^ 1;
            char* base = (char*)smem;
            *(uint4*)(base + SM_AHI + ((nb * 128 + ar0) * APITCH + as0 * 8) * 2) = pah0;
            *(uint4*)(base + SM_AHI + ((nb * 128 + ar1) * APITCH + as1 * 8) * 2) = pah1;
            *(uint4*)(base + SM_ALO + ((nb * 128 + ar0) * APITCH + as0 * 8) * 2) = pal0;
            *(uint4*)(base + SM_ALO + ((nb * 128 + ar1) * APITCH + as1 * 8) * 2) = pal1;
            *(uint4*)(base + SM_BHI + ((nb * 32 + bk0) * BPITCH + bs0 * 8) * 2) = pbh0;
            *(uint4*)(base + SM_BHI + ((nb * 32 + bk1) * BPITCH + bs1 * 8) * 2) = pbh1;
            *(uint4*)(base + SM_BLO + ((nb * 32 + bk0) * BPITCH + bs0 * 8) * 2) = pbl0;
            *(uint4*)(base + SM_BLO + ((nb * 32 + bk1) * BPITCH + bs1 * 8) * 2) = pbl1;
        }
        __syncthreads();
        buf ^= 1;
    }

    int g = lane >> 2, tig = lane & 3;
#pragma unroll
    for (int i = 0; i < 2; i++) {
#pragma unroll
        for (int j = 0; j < 8; j++) {
            int col = colBase + warp_n + j * 8 + tig * 2;
            float2 bv = *(const float2*)(bias + col);
            int r0 = rowBase + warp_m + i * 16 + g;
            float2 o0 = make_float2(acc[i][j][0] + bv.x, acc[i][j][1] + bv.y);
            float2 o1 = make_float2(acc[i][j][2] + bv.x, acc[i][j][3] + bv.y);
            *(float2*)(C + (size_t)r0 * N + col) = o0;
            *(float2*)(C + (size_t)(r0 + 8) * N + col) = o1;
        }
    }
}

// ---------------------------------------------------------------------------
// Tensor-core scores GEMM: S[b] = Q[b] @ K[b]^T  (bf16x3, causal tile skip).
// Both operands are [rows, 512] row-major; for mma.row.col the B fragment
// from [N,K] row-major loads with NON-trans ldmatrix using the A-path lane
// mapping (thread t -> row t>>2, col pair t&3) — so the B side is a clone of
// the A side.  No bias; softmax applies 1/scale and ignores masked entries.
// ---------------------------------------------------------------------------
#define SC_APITCH 40
#define SC_AHI 0
#define SC_ALO 20480
#define SC_BHI 40960
#define SC_BLO 61440
#define SC_SMEM 81920

__global__ void __launch_bounds__(256) scores_mma_kernel(
    const __nv_bfloat16* __restrict__ Qh, const __nv_bfloat16* __restrict__ Ql,
    const __nv_bfloat16* __restrict__ Kh, const __nv_bfloat16* __restrict__ Kl,
    float* __restrict__ S)
{
    extern __shared__ char smem[];
    const int KD = DPROJ;                 // 512 contraction dim
    int tid = threadIdx.x, lane = tid & 31, warp = tid >> 5;
    int bz = blockIdx.z;
    int rowBase = blockIdx.y * 128, colBase = blockIdx.x * 128;
    if (rowBase + 127 < colBase) return;  // fully masked tile
    int warp_m = (warp >> 1) * 32, warp_n = (warp & 1) * 64;

    uint32_t sA = smem_addr_u32(smem);
    uint32_t sAhi = sA + SC_AHI, sAlo = sA + SC_ALO;
    uint32_t sBhi = sA + SC_BHI, sBlo = sA + SC_BLO;

    int q = lane >> 3, r = lane & 7;
    int a_row[2];
    a_row[0] = warp_m + (q & 1) * 8 + r;
    a_row[1] = a_row[0] + 16;
    int a_col = (q >> 1) * 8;
    int b_row[4];
#pragma unroll
    for (int p = 0; p < 4; p++) b_row[p] = warp_n + p * 16 + (q & 1) * 8 + r;

    // loaders: 512 chunks of 8 bf16 per 128x32 tile (row = ch>>2, sub = ch&3)
    int ch0 = tid, ch1 = tid + 256;
    int ar0 = ch0 >> 2, as0 = ch0 & 3, ar1 = ch1 >> 2, as1 = ch1 & 3;

    size_t bbase = (size_t)bz * SEQ;
    const __nv_bfloat16* Ahp0 = Qh + (bbase + rowBase + ar0) * KD + as0 * 8;
    const __nv_bfloat16* Ahp1 = Qh + (bbase + rowBase + ar1) * KD + as1 * 8;
    const __nv_bfloat16* Alp0 = Ql + (bbase + rowBase + ar0) * KD + as0 * 8;
    const __nv_bfloat16* Alp1 = Ql + (bbase + rowBase + ar1) * KD + as1 * 8;
    const __nv_bfloat16* Bhp0 = Kh + (bbase + colBase + ar0) * KD + as0 * 8;
    const __nv_bfloat16* Bhp1 = Kh + (bbase + colBase + ar1) * KD + as1 * 8;
    const __nv_bfloat16* Blp0 = Kl + (bbase + colBase + ar0) * KD + as0 * 8;
    const __nv_bfloat16* Blp1 = Kl + (bbase + colBase + ar1) * KD + as1 * 8;

    float acc[2][8][4];
#pragma unroll
    for (int i = 0; i < 2; i++)
#pragma unroll
        for (int j = 0; j < 8; j++)
#pragma unroll
            for (int v = 0; v < 4; v++) acc[i][j][v] = 0.0f;

    uint4 pah0, pah1, pal0, pal1, pbh0, pbh1, pbl0, pbl1;
    pah0 = *(const uint4*)(Ahp0); pah1 = *(const uint4*)(Ahp1);
    pal0 = *(const uint4*)(Alp0); pal1 = *(const uint4*)(Alp1);
    pbh0 = *(const uint4*)(Bhp0); pbh1 = *(const uint4*)(Bhp1);
    pbl0 = *(const uint4*)(Blp0); pbl1 = *(const uint4*)(Blp1);
    {
        char* base = (char*)smem;
        *(uint4*)(base + SC_AHI + (ar0 * SC_APITCH + as0 * 8) * 2) = pah0;
        *(uint4*)(base + SC_AHI + (ar1 * SC_APITCH + as1 * 8) * 2) = pah1;
        *(uint4*)(base + SC_ALO + (ar0 * SC_APITCH + as0 * 8) * 2) = pal0;
        *(uint4*)(base + SC_ALO + (ar1 * SC_APITCH + as1 * 8) * 2) = pal1;
        *(uint4*)(base + SC_BHI + (ar0 * SC_APITCH + as0 * 8) * 2) = pbh0;
        *(uint4*)(base + SC_BHI + (ar1 * SC_APITCH + as1 * 8) * 2) = pbh1;
        *(uint4*)(base + SC_BLO + (ar0 * SC_APITCH + as0 * 8) * 2) = pbl0;
        *(uint4*)(base + SC_BLO + (ar1 * SC_APITCH + as1 * 8) * 2) = pbl1;
    }
    __syncthreads();

    const int nTiles = KD / 32;   // 16
    int buf = 0;
    for (int kt = 0; kt < nTiles; kt++) {
        bool nxt = (kt + 1 < nTiles);
        if (nxt) {
            int ko = (kt + 1) * 32;
            pah0 = *(const uint4*)(Ahp0 + ko); pah1 = *(const uint4*)(Ahp1 + ko);
            pal0 = *(const uint4*)(Alp0 + ko); pal1 = *(const uint4*)(Alp1 + ko);
            pbh0 = *(const uint4*)(Bhp0 + ko); pbh1 = *(const uint4*)(Bhp1 + ko);
            pbl0 = *(const uint4*)(Blp0 + ko); pbl1 = *(const uint4*)(Blp1 + ko);
        }

#pragma unroll
        for (int ks = 0; ks < 2; ks++) {
            uint32_t aoffh = sAhi + ((buf * 128) * SC_APITCH + ks * 16 + a_col) * 2;
            uint32_t aoffl = sAlo + ((buf * 128) * SC_APITCH + ks * 16 + a_col) * 2;
            uint32_t ahi[2][4], alo[2][4];
#pragma unroll
            for (int i = 0; i < 2; i++) {
                ldsm_x4(ahi[i][0], ahi[i][1], ahi[i][2], ahi[i][3],
                        aoffh + a_row[i] * (SC_APITCH * 2));
                ldsm_x4(alo[i][0], alo[i][1], alo[i][2], alo[i][3],
                        aoffl + a_row[i] * (SC_APITCH * 2));
            }
            // B fragments: regs (q0: n-low/k-low, q1: n-high/k-low,
            //                    q2: n-low/k-high, q3: n-high/k-high)
            uint32_t boffh = sBhi + ((buf * 128) * SC_APITCH + ks * 16 + a_col) * 2;
            uint32_t boffl = sBlo + ((buf * 128) * SC_APITCH + ks * 16 + a_col) * 2;
            uint32_t bhi[4][4], blo[4][4];
#pragma unroll
            for (int p = 0; p < 4; p++) {
                ldsm_x4(bhi[p][0], bhi[p][1], bhi[p][2], bhi[p][3],
                        boffh + b_row[p] * (SC_APITCH * 2));
                ldsm_x4(blo[p][0], blo[p][1], blo[p][2], blo[p][3],
                        boffl + b_row[p] * (SC_APITCH * 2));
            }
#pragma unroll
            for (int i = 0; i < 2; i++) {
#pragma unroll
                for (int p = 0; p < 4; p++) {
#pragma unroll
                    for (int t = 0; t < 2; t++) {
                        int j = p * 2 + t;
                        // n-group t: b0 = reg[t] (k0-7), b1 = reg[t+2] (k8-15)
                        uint32_t b0h = bhi[p][t], b1h = bhi[p][t + 2];
                        uint32_t b0l = blo[p][t], b1l = blo[p][t + 2];
                        mma_bf16(acc[i][j], ahi[i], b0h, b1h);
                        mma_bf16(acc[i][j], ahi[i], b0l, b1l);
                        mma_bf16(acc[i][j], alo[i], b0h, b1h);
                    }
                }
            }
        }

        if (nxt) {
            int nb = buf ^ 1;
            char* base = (char*)smem;
            *(uint4*)(base + SC_AHI + ((nb * 128 + ar0) * SC_APITCH + as0 * 8) * 2) = pah0;
            *(uint4*)(base + SC_AHI + ((nb * 128 + ar1) * SC_APITCH + as1 * 8) * 2) = pah1;
            *(uint4*)(base + SC_ALO + ((nb * 128 + ar0) * SC_APITCH + as0 * 8) * 2) = pal0;
            *(uint4*)(base + SC_ALO + ((nb * 128 + ar1) * SC_APITCH + as1 * 8) * 2) = pal1;
            *(uint4*)(base + SC_BHI + ((nb * 128 + ar0) * SC_APITCH + as0 * 8) * 2) = pbh0;
            *(uint4*)(base + SC_BHI + ((nb * 128 + ar1) * SC_APITCH + as1 * 8) * 2) = pbh1;
            *(uint4*)(base + SC_BLO + ((nb * 128 + ar0) * SC_APITCH + as0 * 8) * 2) = pbl0;
            *(uint4*)(base + SC_BLO + ((nb * 128 + ar1) * SC_APITCH + as1 * 8) * 2) = pbl1;
        }
        __syncthreads();
        buf ^= 1;
    }

    float* Sb = S + (size_t)bz * SEQ * SEQ;
    int g = lane >> 2, tig = lane & 3;
#pragma unroll
    for (int i = 0; i < 2; i++) {
#pragma unroll
        for (int j = 0; j < 8; j++) {
            int col = colBase + warp_n + j * 8 + tig * 2;
            int r0 = rowBase + warp_m + i * 16 + g;
            *(float2*)(Sb + (size_t)r0 * SEQ + col) =
                make_float2(acc[i][j][0], acc[i][j][1]);
            *(float2*)(Sb + (size_t)(r0 + 8) * SEQ + col) =
                make_float2(acc[i][j][2], acc[i][j][3]);
        }
    }
}

// ---------------------------------------------------------------------------
// SGEMM (fp32): PV / G*.
// ---------------------------------------------------------------------------
__global__ void __launch_bounds__(256, 2) sgemm128(
    const float* __restrict__ A, const float* __restrict__ B,
    const float* __restrict__ bias, float* __restrict__ C,
    int M, int N, int K,
    size_t sA, size_t sB, size_t sC,
    int transB, int mode)
{
    constexpr int BM = 128, BN = 128, BK = 16, PAD = 4;
    __shared__ float As[2][BK][BM + PAD];
    __shared__ float Bs[2][BK][BN + PAD];

    int bx = blockIdx.x, by = blockIdx.y, bz = blockIdx.z;
    int rowBase = by * BM, colBase = bx * BN;
    if (mode == 1 && rowBase + BM - 1 < colBase) return;
    int Kend = K;
    if (mode == 2) Kend = (rowBase + BM < K) ? rowBase + BM : K;

    const float* Ab = A + sA * (size_t)bz;
    const float* Bb = B + sB * (size_t)bz;
    float*       Cb = C + sC * (size_t)bz;

    int tid = threadIdx.x;
    int ty = tid >> 4, tx = tid & 15;
    int row0 = ty * 8;
    int c0 = tx * 4, c1 = 64 + tx * 4;

    int arow = tid >> 1, akof = (tid & 1) * 8;
    const float* aptr = Ab + (size_t)(rowBase + arow) * K + akof;

    int bkr = tid >> 4, bnc = (tid & 15) * 8;
    int bnr = tid >> 1, bkof = (tid & 1) * 8;
    const float* bptr = transB
        ? Bb + (size_t)(colBase + bnr) * K + bkof
        : Bb + (size_t)bkr * N + colBase + bnc;

    float acc[8][8];
#pragma unroll
    for (int i = 0; i < 8; i++)
#pragma unroll
        for (int j = 0; j < 8; j++) acc[i][j] = 0.0f;

    int nTiles = Kend / BK;

    {
        float4 a0 = *(const float4*)(aptr);
        float4 a1 = *(const float4*)(aptr + 4);
        As[0][akof + 0][arow] = a0.x; As[0][akof + 1][arow] = a0.y;
        As[0][akof + 2][arow] = a0.z; As[0][akof + 3][arow] = a0.w;
        As[0][akof + 4][arow] = a1.x; As[0][akof + 5][arow] = a1.y;
        As[0][akof + 6][arow] = a1.z; As[0][akof + 7][arow] = a1.w;
        float4 b0 = *(const float4*)(bptr);
        float4 b1 = *(const float4*)(bptr + 4);
        if (!transB) {
            *(float4*)&Bs[0][bkr][bnc]     = b0;
            *(float4*)&Bs[0][bkr][bnc + 4] = b1;
        } else {
            Bs[0][bkof + 0][bnr] = b0.x; Bs[0][bkof + 1][bnr] = b0.y;
            Bs[0][bkof + 2][bnr] = b0.z; Bs[0][bkof + 3][bnr] = b0.w;
            Bs[0][bkof + 4][bnr] = b1.x; Bs[0][bkof + 5][bnr] = b1.y;
            Bs[0][bkof + 6][bnr] = b1.z; Bs[0][bkof + 7][bnr] = b1.w;
        }
    }
    __syncthreads();

    int buf = 0;
    for (int t0 = 0; t0 < nTiles; t0++) {
        float4 na0, na1, nb0, nb1;
        bool nxt = (t0 + 1 < nTiles);
        if (nxt) {
            const float* ap = aptr + (t0 + 1) * BK;
            na0 = *(const float4*)(ap);
            na1 = *(const float4*)(ap + 4);
            const float* bp = transB ? bptr + (t0 + 1) * BK
                                     : bptr + (size_t)(t0 + 1) * BK * N;
            nb0 = *(const float4*)(bp);
            nb1 = *(const float4*)(bp + 4);
        }

        float4 fa0 = *(const float4*)&As[buf][0][row0];
        float4 fa1 = *(const float4*)&As[buf][0][row0 + 4];
        float4 fb0 = *(const float4*)&Bs[buf][0][c0];
        float4 fb1 = *(const float4*)&Bs[buf][0][c1];
#pragma unroll
        for (int kk = 0; kk < BK; kk++) {
            float4 ga0, ga1, gb0, gb1;
            if (kk < BK - 1) {
                ga0 = *(const float4*)&As[buf][kk + 1][row0];
                ga1 = *(const float4*)&As[buf][kk + 1][row0 + 4];
                gb0 = *(const float4*)&Bs[buf][kk + 1][c0];
                gb1 = *(const float4*)&Bs[buf][kk + 1][c1];
            }
            float a[8] = {fa0.x, fa0.y, fa0.z, fa0.w, fa1.x, fa1.y, fa1.z, fa1.w};
            float b[8] = {fb0.x, fb0.y, fb0.z, fb0.w, fb1.x, fb1.y, fb1.z, fb1.w};
#pragma unroll
            for (int i = 0; i < 8; i++)
#pragma unroll
                for (int j = 0; j < 8; j++)
                    acc[i][j] = fmaf(a[i], b[j], acc[i][j]);
            if (kk < BK - 1) { fa0 = ga0; fa1 = ga1; fb0 = gb0; fb1 = gb1; }
        }

        if (nxt) {
            int nb = buf ^ 1;
            As[nb][akof + 0][arow] = na0.x; As[nb][akof + 1][arow] = na0.y;
            As[nb][akof + 2][arow] = na0.z; As[nb][akof + 3][arow] = na0.w;
            As[nb][akof + 4][arow] = na1.x; As[nb][akof + 5][arow] = na1.y;
            As[nb][akof + 6][arow] = na1.z; As[nb][akof + 7][arow] = na1.w;
            if (!transB) {
                *(float4*)&Bs[nb][bkr][bnc]     = nb0;
                *(float4*)&Bs[nb][bkr][bnc + 4] = nb1;
            } else {
                Bs[nb][bkof + 0][bnr] = nb0.x; Bs[nb][bkof + 1][bnr] = nb0.y;
                Bs[nb][bkof + 2][bnr] = nb0.z; Bs[nb][bkof + 3][bnr] = nb0.w;
                Bs[nb][bkof + 4][bnr] = nb1.x; Bs[nb][bkof + 5][bnr] = nb1.y;
                Bs[nb][bkof + 6][bnr] = nb1.z; Bs[nb][bkof + 7][bnr] = nb1.w;
            }
        }
        __syncthreads();
        buf ^= 1;
    }

    float4 bv0 = make_float4(0.f, 0.f, 0.f, 0.f);
    float4 bv1 = bv0;
    if (bias) {
        bv0 = *(const float4*)(bias + colBase + c0);
        bv1 = *(const float4*)(bias + colBase + c1);
    }
#pragma unroll
    for (int i = 0; i < 8; i++) {
        size_t row = (size_t)(rowBase + row0 + i);
        float4 o0 = make_float4(acc[i][0] + bv0.x, acc[i][1] + bv0.y,
                                acc[i][2] + bv0.z, acc[i][3] + bv0.w);
        float4 o1 = make_float4(acc[i][4] + bv1.x, acc[i][5] + bv1.y,
                                acc[i][6] + bv1.z, acc[i][7] + bv1.w);
        *(float4*)(Cb + row * N + colBase + c0) = o0;
        *(float4*)(Cb + row * N + colBase + c1) = o1;
    }
}

// ---------------------------------------------------------------------------
// Causal row softmax, in place.
// ---------------------------------------------------------------------------
__global__ void softmax_causal_kernel()
{
    int r = blockIdx.x, b = blockIdx.y;
    float* row = g_S + ((size_t)b * SEQ + r) * SEQ;
    int len = r + 1;
    int tid = threadIdx.x;
    __shared__ float buf[SEQ];
    __shared__ float red[256];
    const float inv = rsqrtf(512.0f);

    float m = -3.4e38f;
    for (int i = tid; i < len; i += 256) m = fmaxf(m, row[i]);
    red[tid] = m; __syncthreads();
    for (int s = 128; s; s >>= 1) { if (tid < s) red[tid] = fmaxf(red[tid], red[tid + s]); __syncthreads(); }
    m = red[0] * inv;
    __syncthreads();

    float ssum = 0.0f;
    for (int i = tid; i < len; i += 256) {
        float e = __expf(row[i] * inv - m);
        buf[i] = e;
        ssum += e;
    }
    red[tid] = ssum; __syncthreads();
    for (int s = 128; s; s >>= 1) { if (tid < s) red[tid] += red[tid + s]; __syncthreads(); }
    float denom = 1.0f / red[0];
    __syncthreads();

    for (int i = tid; i < SEQ; i += 256)
        row[i] = (i < len) ? buf[i] * denom : 0.0f;
}

// ---------------------------------------------------------------------------
// Prefix pooling + h0.
// ---------------------------------------------------------------------------
__global__ void pool_kernel(const float* __restrict__ Wscore,
                            const float* __restrict__ Wp2h,
                            const float* __restrict__ bp2h)
{
    int b = blockIdx.x;
    const float* feat = g_feat + (size_t)b * SEQ * DPROJ;
    __shared__ float wsc[512];
    __shared__ float sc[512];
    __shared__ float pooled[512];
    __shared__ float red[256];
    int tid = threadIdx.x;

    for (int i = tid; i < 512; i += 256) wsc[i] = Wscore[i];
    __syncthreads();

    int w = tid >> 5, l = tid & 31;
    for (int u = w; u < ASSIST; u += 8) {
        float s = 0.0f;
        for (int p = l; p < DPROJ; p += 32)
            s = fmaf(feat[(size_t)u * DPROJ + p], wsc[p], s);
#pragma unroll
        for (int o = 16; o; o >>= 1) s += __shfl_xor_sync(0xffffffffu, s, o);
        if (l == 0) sc[u] = s;
    }
    __syncthreads();

    float m = fmaxf(sc[tid], sc[tid + 256]);
    red[tid] = m; __syncthreads();
    for (int s = 128; s; s >>= 1) { if (tid < s) red[tid] = fmaxf(red[tid], red[tid + s]); __syncthreads(); }
    m = red[0]; __syncthreads();

    float e0 = expf(sc[tid] - m), e1 = expf(sc[tid + 256] - m);
    red[tid] = e0 + e1; __syncthreads();
    for (int s = 128; s; s >>= 1) { if (tid < s) red[tid] += red[tid + s]; __syncthreads(); }
    float inv = 1.0f / red[0];
    __syncthreads();
    sc[tid] = e0 * inv; sc[tid + 256] = e1 * inv;
    __syncthreads();

    for (int p = tid; p < DPROJ; p += 256) {
        float acc = 0.0f;
        for (int u = 0; u < ASSIST; u++)
            acc = fmaf(sc[u], feat[(size_t)u * DPROJ + p], acc);
        pooled[p] = acc;
    }
    __syncthreads();

    for (int c = tid; c < DMEM; c += 256) {
        float acc = bp2h[c];
        for (int k = 0; k < DPROJ; k++)
            acc = fmaf(pooled[k], Wp2h[(size_t)k * DMEM + c], acc);
        g_h[b * DMEM + c] = tanhf(acc);
    }
}

__global__ void init_out_kernel(float* __restrict__ out, const float* __restrict__ bmem)
{
    int i = blockIdx.x * blockDim.x + threadIdx.x;
    if (i < BATCH * RUN) out[i] = bmem[0];
}

// ---------------------------------------------------------------------------
// Cluster-based sequential scan — EXACT R11 (best known: part[]-smem
// reductions, 64-thread reducers, 1 atomic/CTA, 2 cluster.syncs/step).
// ---------------------------------------------------------------------------
#define SCAN_THREADS 512
#define CL 16

#define H_OFF    0                 // float[512]        2048
#define RH_OFF   2048              // float[512]        2048
#define PART_OFF 4096              // float2[512]       4096
#define WM_OFF   8192              // float[32]          128
#define SCAN_SMEM 8320

__device__ __forceinline__ uint32_t mapa_rank(uint32_t saddr, uint32_t rank) {
    uint32_t r;
    asm("mapa.shared::cluster.u32 %0, %1, %2;" : "=r"(r) : "r"(saddr), "r"(rank));
    return r;
}
__device__ __forceinline__ void stc_f32(uint32_t addr, float v) {
    asm volatile("st.shared::cluster.f32 [%0], %1;" :: "r"(addr), "f"(v));
}
#define CLUSTER_SYNC() do { \
    asm volatile("barrier.cluster.arrive.aligned;" ::: "memory"); \
    asm volatile("barrier.cluster.wait.aligned;" ::: "memory"); \
} while (0)

__global__ void __launch_bounds__(SCAN_THREADS, 1) scan_cluster(
    const float* __restrict__ Uz, const float* __restrict__ Ur,
    const float* __restrict__ Uh, const float* __restrict__ Wmem,
    const float* __restrict__ Gz, const float* __restrict__ Gr,
    const float* __restrict__ Gh, float* __restrict__ out)
{
    extern __shared__ char smem[];
    float*  h_s  = (float*)(smem + H_OFF);
    float*  rh_s = (float*)(smem + RH_OFF);
    float2* part = (float2*)(smem + PART_OFF);
    float*  wm_s = (float*)(smem + WM_OFF);

    int tid = threadIdx.x;
    int c   = tid & 31;
    int seg = tid >> 5;
    int kbase = seg * 32;

    uint32_t rank;
    asm("mov.u32 %0, %%cluster_ctarank;" : "=r"(rank));
    int cg0 = (int)rank * 32;
    int gb  = blockIdx.x >> 4;

    float uz[32], ur[32], uh[32];
#pragma unroll
    for (int i = 0; i < 32; i++) {
        uz[i] = Uz[(size_t)(kbase + i) * DMEM + cg0 + c];
        ur[i] = Ur[(size_t)(kbase + i) * DMEM + cg0 + c];
        uh[i] = Uh[(size_t)(kbase + i) * DMEM + cg0 + c];
    }
    if (tid < 32) wm_s[tid] = Wmem[cg0 + tid];

    h_s[tid] = __ldcg(&g_h[(size_t)gb * DMEM + tid]);
    __syncthreads();

    uint32_t rh_base = smem_addr_u32(rh_s);
    uint32_t h_base  = smem_addr_u32(h_s);

    const float dtc = 1.0f / 1535.0f;
    float zreg = 0.0f;

    for (int t = 0; t < RUN; t++) {
        float dtv = (t == 0) ? 0.0f : dtc;

        float gA = 0.0f, gH = 0.0f;
        if (tid < 64) {
            int cc = tid & 31, mat = tid >> 5;
            const float* P = mat ? Gr : Gz;
            gA = __ldg(&P[((size_t)(gb * RUN + t)) * DMEM + cg0 + cc]);
        }
        if (tid < 32) {
            gH = __ldg(&Gh[((size_t)(gb * RUN + t)) * DMEM + cg0 + tid]);
        }

        float pz = 0.f, pr = 0.f;
        const float4* hp = (const float4*)&h_s[kbase];
#pragma unroll
        for (int i = 0; i < 8; i++) {
            float4 h4 = hp[i];
            pz = fmaf(h4.x, uz[4*i+0], pz); pr = fmaf(h4.x, ur[4*i+0], pr);
            pz = fmaf(h4.y, uz[4*i+1], pz); pr = fmaf(h4.y, ur[4*i+1], pr);
            pz = fmaf(h4.z, uz[4*i+2], pz); pr = fmaf(h4.z, ur[4*i+2], pr);
            pz = fmaf(h4.w, uz[4*i+3], pz); pr = fmaf(h4.w, ur[4*i+3], pr);
        }
        part[tid] = make_float2(pz, pr);
        __syncthreads();

        if (tid < 64) {
            int cc = tid & 31, mat = tid >> 5;
            float s = 0.0f;
#pragma unroll
            for (int sg = 0; sg < 16; sg++) {
                float2 p = part[sg * 32 + cc];
                s += mat ? p.y : p.x;
            }
            float v = gA + s;
            float sig = 1.0f / (1.0f + __expf(-v));
            if (mat == 0) {
                zreg = sig;
            } else {
                float rhv = sig * h_s[cg0 + cc];
                uint32_t a = rh_base + (uint32_t)(cg0 + cc) * 4u;
#pragma unroll
                for (int rk = 0; rk < CL; rk++)
                    stc_f32(mapa_rank(a, (uint32_t)rk), rhv);
            }
        }
        CLUSTER_SYNC();

        float ph = 0.f;
        const float4* rp = (const float4*)&rh_s[kbase];
#pragma unroll
        for (int i = 0; i < 8; i++) {
            float4 r4 = rp[i];
            ph = fmaf(r4.x, uh[4*i+0], ph);
            ph = fmaf(r4.y, uh[4*i+1], ph);
            ph = fmaf(r4.z, uh[4*i+2], ph);
            ph = fmaf(r4.w, uh[4*i+3], ph);
        }
        part[tid].x = ph;
        __syncthreads();

        if (tid < 32) {
            int cc = tid;
            float s = 0.0f;
#pragma unroll
            for (int sg = 0; sg < 16; sg++)
                s += part[sg * 32 + cc].x;
            float hh   = tanhf(gH + s);
            int   cg   = cg0 + cc;
            float hold = h_s[cg];
            float hnew = hold + zreg * (hh - hold);
            float hout = hnew + dtv * (hnew - hold);
            if (t < RUN - 1) {
                uint32_t a = h_base + (uint32_t)cg * 4u;
#pragma unroll
                for (int rk = 0; rk < CL; rk++)
                    stc_f32(mapa_rank(a, (uint32_t)rk), hout);
            }
            float lv = hout * wm_s[cc];
#pragma unroll
            for (int o = 16; o; o >>= 1)
                lv += __shfl_xor_sync(0xffffffffu, lv, o);
            if (cc == 0)
                atomicAdd(&out[gb * RUN + t], lv);
        }
        CLUSTER_SYNC();
    }
}

// ---------------------------------------------------------------------------
// Host
// ---------------------------------------------------------------------------
extern "C" void kernel_launch(void* const* d_in, const int* in_sizes, int n_in,
                              void* d_out, int out_size)
{
    const float* x      = (const float*)d_in[0];
    const float* Wq     = (const float*)d_in[1];
    const float* bq     = (const float*)d_in[2];
    const float* Wk     = (const float*)d_in[3];
    const float* bk     = (const float*)d_in[4];
    const float* Wv     = (const float*)d_in[5];
    const float* bv     = (const float*)d_in[6];
    const float* Wz     = (const float*)d_in[7];
    const float* Uz     = (const float*)d_in[8];
    const float* bz     = (const float*)d_in[9];
    const float* Wr     = (const float*)d_in[10];
    const float* Ur     = (const float*)d_in[11];
    const float* br     = (const float*)d_in[12];
    const float* Wh     = (const float*)d_in[13];
    const float* Uh     = (const float*)d_in[14];
    const float* bh     = (const float*)d_in[15];
    const float* Wmem   = (const float*)d_in[16];
    const float* bmem   = (const float*)d_in[17];
    const float* Wp2h   = (const float*)d_in[18];
    const float* bp2h   = (const float*)d_in[19];
    const float* Wscore = (const float*)d_in[20];
    (void)in_sizes; (void)n_in;
    float* out = (float*)d_out;

    float *pQ, *pK, *pV, *pS, *pF, *pGz, *pGr, *pGh;
    cudaGetSymbolAddress((void**)&pQ,  g_Q);
    cudaGetSymbolAddress((void**)&pK,  g_K);
    cudaGetSymbolAddress((void**)&pV,  g_V);
    cudaGetSymbolAddress((void**)&pS,  g_S);
    cudaGetSymbolAddress((void**)&pF,  g_feat);
    cudaGetSymbolAddress((void**)&pGz, g_Gz);
    cudaGetSymbolAddress((void**)&pGr, g_Gr);
    cudaGetSymbolAddress((void**)&pGh, g_Gh);

    __nv_bfloat16 *pxh, *pxl, *pWh, *pWl;
    cudaGetSymbolAddress((void**)&pxh, g_xhi);
    cudaGetSymbolAddress((void**)&pxl, g_xlo);
    cudaGetSymbolAddress((void**)&pWh, g_Whi);
    cudaGetSymbolAddress((void**)&pWl, g_Wlo);

    dim3 t256(256);
    const size_t WSZ = (size_t)DIN * DPROJ;
    const size_t QKSZ = (size_t)ROWS * DPROJ;   // 4M elements

    // split x and W into bf16 (hi, lo)
    split_kernel<<<2048, t256>>>(x,  pxh, pxl, (size_t)ROWS * DIN / 4);
    split_kernel<<<512,  t256>>>(Wq, pWh,           pWl,           WSZ / 4);
    split_kernel<<<512,  t256>>>(Wk, pWh + WSZ,     pWl + WSZ,     WSZ / 4);
    split_kernel<<<512,  t256>>>(Wv, pWh + 2 * WSZ, pWl + 2 * WSZ, WSZ / 4);

    // tensor-core QKV projections
    cudaFuncSetAttribute(qkv_mma_kernel,
                         cudaFuncAttributeMaxDynamicSharedMemorySize, QKV_SMEM);
    {
        dim3 g(DPROJ / 128, ROWS / 128, 1);
        qkv_mma_kernel<<<g, t256, QKV_SMEM>>>(pxh, pxl, pWh,           pWl,           bq, pQ);
        qkv_mma_kernel<<<g, t256, QKV_SMEM>>>(pxh, pxl, pWh + WSZ,     pWl + WSZ,     bk, pK);
        qkv_mma_kernel<<<g, t256, QKV_SMEM>>>(pxh, pxl, pWh + 2 * WSZ, pWl + 2 * WSZ, bv, pV);
    }

    // split Q and K (reuse g_xhi region: 4 x 4M bf16 fits in ROWS*DIN)
    __nv_bfloat16* pQh = pxh;
    __nv_bfloat16* pQl = pxh + QKSZ;
    __nv_bfloat16* pKh = pxh + 2 * QKSZ;
    __nv_bfloat16* pKl = pxh + 3 * QKSZ;
    split_kernel<<<1024, t256>>>(pQ, pQh, pQl, QKSZ / 4);
    split_kernel<<<1024, t256>>>(pK, pKh, pKl, QKSZ / 4);

    // scores = Q K^T via tensor cores (causal tile skip)
    cudaFuncSetAttribute(scores_mma_kernel,
                         cudaFuncAttributeMaxDynamicSharedMemorySize, SC_SMEM);
    {
        dim3 g(SEQ / 128, SEQ / 128, BATCH);
        scores_mma_kernel<<<g, t256, SC_SMEM>>>(pQh, pQl, pKh, pKl, pS);
    }

    softmax_causal_kernel<<<dim3(SEQ, BATCH), t256>>>();

    // feat = P V (K-limited: P lower-triangular)
    {
        dim3 g(DPROJ / 128, SEQ / 128, BATCH);
        sgemm128<<<g, t256>>>(pS, pV, nullptr, pF, SEQ, DPROJ, SEQ,
                              (size_t)SEQ * SEQ, (size_t)SEQ * DPROJ,
                              (size_t)SEQ * DPROJ, 0, 2);
    }

    pool_kernel<<<BATCH, t256>>>(Wscore, Wp2h, bp2h);

    // G* = feat_assist @ W* + b*
    {
        dim3 g(DMEM / 128, RUN / 128, BATCH);
        const float* Aoff = pF + (size_t)ASSIST * DPROJ;
        sgemm128<<<g, t256>>>(Aoff, Wz, bz, pGz, RUN, DMEM, DPROJ,
                              (size_t)SEQ * DPROJ, 0, (size_t)RUN * DMEM, 0, 0);
        sgemm128<<<g, t256>>>(Aoff, Wr, br, pGr, RUN, DMEM, DPROJ,
                              (size_t)SEQ * DPROJ, 0, (size_t)RUN * DMEM, 0, 0);
        sgemm128<<<g, t256>>>(Aoff, Wh, bh, pGh, RUN, DMEM, DPROJ,
                              (size_t)SEQ * DPROJ, 0, (size_t)RUN * DMEM, 0, 0);
    }

    init_out_kernel<<<(BATCH * RUN + 255) / 256, t256>>>(out, bmem);

    // cluster scan: 4 clusters x 16 CTAs x 512 threads (1 batch / cluster)
    cudaFuncSetAttribute(scan_cluster,
                         cudaFuncAttributeMaxDynamicSharedMemorySize, SCAN_SMEM);
    cudaFuncSetAttribute(scan_cluster,
                         cudaFuncAttributeNonPortableClusterSizeAllowed, 1);
    {
        cudaLaunchConfig_t cfg = {};
        cfg.gridDim  = dim3(64, 1, 1);
        cfg.blockDim = dim3(SCAN_THREADS, 1, 1);
        cfg.dynamicSmemBytes = SCAN_SMEM;
        cfg.stream = 0;
        cudaLaunchAttribute attrs[1];
        attrs[0].id = cudaLaunchAttributeClusterDimension;
        attrs[0].val.clusterDim.x = CL;
        attrs[0].val.clusterDim.y = 1;
        attrs[0].val.clusterDim.z = 1;
        cfg.attrs = attrs;
        cfg.numAttrs = 1;
        cudaLaunchKernelEx(&cfg, scan_cluster,
                           Uz, Ur, Uh, Wmem,
                           (const float*)pGz, (const float*)pGr,
                           (const float*)pGh, out);
    }

    (void)out_size;
}

// round 15
// speedup vs baseline: 2.5576x; 1.0610x over previous
#include <cuda_runtime.h>
#include <cuda_bf16.h>
#include <math.h>
#include <stdint.h>

// ---------------------------------------------------------------------------
// Problem constants
// ---------------------------------------------------------------------------
#define BATCH   4
#define SEQ     2048
#define DIN     4096
#define DPROJ   512
#define DMEM    512
#define ASSIST  512
#define RUN     1536
#define ROWS    (BATCH*SEQ)   // 8192

// ---------------------------------------------------------------------------
// Device scratch
// ---------------------------------------------------------------------------
__device__ float g_Q[(size_t)ROWS*DPROJ];
__device__ float g_K[(size_t)ROWS*DPROJ];
__device__ float g_V[(size_t)ROWS*DPROJ];
__device__ float g_S[(size_t)BATCH*SEQ*SEQ];
__device__ float g_feat[(size_t)ROWS*DPROJ];
__device__ float g_Gz[(size_t)BATCH*RUN*DMEM];
__device__ float g_Gr[(size_t)BATCH*RUN*DMEM];
__device__ float g_Gh[(size_t)BATCH*RUN*DMEM];
__device__ float g_h[BATCH*DMEM];

// bf16 split operands
__device__ __nv_bfloat16 g_xhi[(size_t)ROWS*DIN];
__device__ __nv_bfloat16 g_xlo[(size_t)ROWS*DIN];
__device__ __nv_bfloat16 g_Whi[3][(size_t)DIN*DPROJ];
__device__ __nv_bfloat16 g_Wlo[3][(size_t)DIN*DPROJ];
// P (softmax output) hi/lo, V hi/lo, feat-assist hi/lo, small W hi/lo
__device__ __nv_bfloat16 g_Phi[(size_t)BATCH*SEQ*SEQ];
__device__ __nv_bfloat16 g_Plo[(size_t)BATCH*SEQ*SEQ];
__device__ __nv_bfloat16 g_Vh[(size_t)ROWS*DPROJ];
__device__ __nv_bfloat16 g_Vl[(size_t)ROWS*DPROJ];
__device__ __nv_bfloat16 g_fah[(size_t)BATCH*RUN*DMEM];
__device__ __nv_bfloat16 g_fal[(size_t)BATCH*RUN*DMEM];
__device__ __nv_bfloat16 g_Uwh[3][(size_t)DPROJ*DMEM];
__device__ __nv_bfloat16 g_Uwl[3][(size_t)DPROJ*DMEM];

// ---------------------------------------------------------------------------
// Split fp32 -> (hi, lo) bf16.
// ---------------------------------------------------------------------------
__global__ void split_kernel(const float* __restrict__ src,
                             __nv_bfloat16* __restrict__ hi,
                             __nv_bfloat16* __restrict__ lo, size_t n4)
{
    size_t i = (size_t)blockIdx.x * blockDim.x + threadIdx.x;
    size_t stride = (size_t)gridDim.x * blockDim.x;
    for (; i < n4; i += stride) {
        float4 v = ((const float4*)src)[i];
        __nv_bfloat16 h0 = __float2bfloat16(v.x);
        __nv_bfloat16 h1 = __float2bfloat16(v.y);
        __nv_bfloat16 h2 = __float2bfloat16(v.z);
        __nv_bfloat16 h3 = __float2bfloat16(v.w);
        __nv_bfloat162 hh0 = {h0, h1}, hh1 = {h2, h3};
        __nv_bfloat162 ll0 = {__float2bfloat16(v.x - __bfloat162float(h0)),
                              __float2bfloat16(v.y - __bfloat162float(h1))};
        __nv_bfloat162 ll1 = {__float2bfloat16(v.z - __bfloat162float(h2)),
                              __float2bfloat16(v.w - __bfloat162float(h3))};
        ((__nv_bfloat162*)hi)[i * 2]     = hh0;
        ((__nv_bfloat162*)hi)[i * 2 + 1] = hh1;
        ((__nv_bfloat162*)lo)[i * 2]     = ll0;
        ((__nv_bfloat162*)lo)[i * 2 + 1] = ll1;
    }
}

// ---------------------------------------------------------------------------
// MMA helpers
// ---------------------------------------------------------------------------
__device__ __forceinline__ uint32_t smem_addr_u32(const void* p) {
    uint32_t a;
    asm("{ .reg .u64 t; cvta.to.shared.u64 t, %1; cvt.u32.u64 %0, t; }"
        : "=r"(a) : "l"(p));
    return a;
}
__device__ __forceinline__ void ldsm_x4(uint32_t& r0, uint32_t& r1,
                                        uint32_t& r2, uint32_t& r3, uint32_t a) {
    asm volatile("ldmatrix.sync.aligned.m8n8.x4.shared.b16 {%0,%1,%2,%3}, [%4];"
                 : "=r"(r0), "=r"(r1), "=r"(r2), "=r"(r3) : "r"(a));
}
__device__ __forceinline__ void ldsm_x4_t(uint32_t& r0, uint32_t& r1,
                                          uint32_t& r2, uint32_t& r3, uint32_t a) {
    asm volatile("ldmatrix.sync.aligned.m8n8.x4.trans.shared.b16 {%0,%1,%2,%3}, [%4];"
                 : "=r"(r0), "=r"(r1), "=r"(r2), "=r"(r3) : "r"(a));
}
__device__ __forceinline__ void mma_bf16(float* d, const uint32_t* a,
                                         uint32_t b0, uint32_t b1) {
    asm volatile(
        "mma.sync.aligned.m16n8k16.row.col.f32.bf16.bf16.f32 "
        "{%0,%1,%2,%3}, {%4,%5,%6,%7}, {%8,%9}, {%0,%1,%2,%3};"
        : "+f"(d[0]), "+f"(d[1]), "+f"(d[2]), "+f"(d[3])
        : "r"(a[0]), "r"(a[1]), "r"(a[2]), "r"(a[3]), "r"(b0), "r"(b1));
}

#define APITCH 40
#define BPITCH 136
#define SM_AHI 0
#define SM_ALO 20480
#define SM_BHI 40960
#define SM_BLO 58368
#define QKV_SMEM 75776

// ---------------------------------------------------------------------------
// Generalized batched bf16x3 GEMM: C[bz] = A[bz][M,K] @ B[bz][K,N] (+bias)
//   A row-major bf16 hi/lo, B row-major bf16 hi/lo, fp32 C.
//   mode2: Kend = min(rowBase+128, K) (A rows lower-triangular vs K, e.g. PV)
//   Used for QKV (strides 0 on B), PV (P @ V), G* (feat @ W*).
// ---------------------------------------------------------------------------
__global__ void __launch_bounds__(256) mma_gemm_gen(
    const __nv_bfloat16* __restrict__ Ah, const __nv_bfloat16* __restrict__ Al,
    const __nv_bfloat16* __restrict__ Bh, const __nv_bfloat16* __restrict__ Bl,
    const float* __restrict__ bias, float* __restrict__ C,
    int N, int K,
    size_t aStride, size_t bStride, size_t cStride, int mode2)
{
    extern __shared__ char smem[];
    int tid = threadIdx.x, lane = tid & 31, warp = tid >> 5;
    int bz = blockIdx.z;
    int rowBase = blockIdx.y * 128, colBase = blockIdx.x * 128;
    int Kend = K;
    if (mode2) Kend = (rowBase + 128 < K) ? rowBase + 128 : K;
    int warp_m = (warp >> 1) * 32, warp_n = (warp & 1) * 64;

    Ah += aStride * (size_t)bz;  Al += aStride * (size_t)bz;
    Bh += bStride * (size_t)bz;  Bl += bStride * (size_t)bz;
    C  += cStride * (size_t)bz;

    uint32_t sA = smem_addr_u32(smem);
    uint32_t sAhi = sA + SM_AHI, sAlo = sA + SM_ALO;
    uint32_t sBhi = sA + SM_BHI, sBlo = sA + SM_BLO;

    int q = lane >> 3, r = lane & 7;
    int a_row[2];
    a_row[0] = warp_m + (q & 1) * 8 + r;
    a_row[1] = a_row[0] + 16;
    int a_col = (q >> 1) * 8;
    int b_k = (q & 1) * 8 + r;
    int b_n[4];
#pragma unroll
    for (int p = 0; p < 4; p++) b_n[p] = warp_n + p * 16 + (q >> 1) * 8;

    int a_ch0 = tid, a_ch1 = tid + 256;
    int ar0 = a_ch0 >> 2, as0 = a_ch0 & 3, ar1 = a_ch1 >> 2, as1 = a_ch1 & 3;
    int bk0 = a_ch0 >> 4, bs0 = a_ch0 & 15, bk1 = a_ch1 >> 4, bs1 = a_ch1 & 15;

    const __nv_bfloat16* Ahp0 = Ah + (size_t)(rowBase + ar0) * K + as0 * 8;
    const __nv_bfloat16* Ahp1 = Ah + (size_t)(rowBase + ar1) * K + as1 * 8;
    const __nv_bfloat16* Alp0 = Al + (size_t)(rowBase + ar0) * K + as0 * 8;
    const __nv_bfloat16* Alp1 = Al + (size_t)(rowBase + ar1) * K + as1 * 8;
    const __nv_bfloat16* Bhp0 = Bh + (size_t)bk0 * N + colBase + bs0 * 8;
    const __nv_bfloat16* Bhp1 = Bh + (size_t)bk1 * N + colBase + bs1 * 8;
    const __nv_bfloat16* Blp0 = Bl + (size_t)bk0 * N + colBase + bs0 * 8;
    const __nv_bfloat16* Blp1 = Bl + (size_t)bk1 * N + colBase + bs1 * 8;

    float acc[2][8][4];
#pragma unroll
    for (int i = 0; i < 2; i++)
#pragma unroll
        for (int j = 0; j < 8; j++)
#pragma unroll
            for (int v = 0; v < 4; v++) acc[i][j][v] = 0.0f;

    uint4 pah0, pah1, pal0, pal1, pbh0, pbh1, pbl0, pbl1;
    pah0 = *(const uint4*)(Ahp0); pah1 = *(const uint4*)(Ahp1);
    pal0 = *(const uint4*)(Alp0); pal1 = *(const uint4*)(Alp1);
    pbh0 = *(const uint4*)(Bhp0); pbh1 = *(const uint4*)(Bhp1);
    pbl0 = *(const uint4*)(Blp0); pbl1 = *(const uint4*)(Blp1);
    {
        char* base = (char*)smem;
        *(uint4*)(base + SM_AHI + (ar0 * APITCH + as0 * 8) * 2) = pah0;
        *(uint4*)(base + SM_AHI + (ar1 * APITCH + as1 * 8) * 2) = pah1;
        *(uint4*)(base + SM_ALO + (ar0 * APITCH + as0 * 8) * 2) = pal0;
        *(uint4*)(base + SM_ALO + (ar1 * APITCH + as1 * 8) * 2) = pal1;
        *(uint4*)(base + SM_BHI + (bk0 * BPITCH + bs0 * 8) * 2) = pbh0;
        *(uint4*)(base + SM_BHI + (bk1 * BPITCH + bs1 * 8) * 2) = pbh1;
        *(uint4*)(base + SM_BLO + (bk0 * BPITCH + bs0 * 8) * 2) = pbl0;
        *(uint4*)(base + SM_BLO + (bk1 * BPITCH + bs1 * 8) * 2) = pbl1;
    }
    __syncthreads();

    const int nTiles = Kend / 32;
    int buf = 0;
    for (int kt = 0; kt < nTiles; kt++) {
        bool nxt = (kt + 1 < nTiles);
        if (nxt) {
            int ko = (kt + 1) * 32;
            pah0 = *(const uint4*)(Ahp0 + ko); pah1 = *(const uint4*)(Ahp1 + ko);
            pal0 = *(const uint4*)(Alp0 + ko); pal1 = *(const uint4*)(Alp1 + ko);
            pbh0 = *(const uint4*)(Bhp0 + (size_t)ko * N);
            pbh1 = *(const uint4*)(Bhp1 + (size_t)ko * N);
            pbl0 = *(const uint4*)(Blp0 + (size_t)ko * N);
            pbl1 = *(const uint4*)(Blp1 + (size_t)ko * N);
        }

#pragma unroll
        for (int ks = 0; ks < 2; ks++) {
            uint32_t aoffh = sAhi + ((buf * 128) * APITCH + ks * 16 + a_col) * 2;
            uint32_t aoffl = sAlo + ((buf * 128) * APITCH + ks * 16 + a_col) * 2;
            uint32_t ahi[2][4], alo[2][4];
#pragma unroll
            for (int i = 0; i < 2; i++) {
                ldsm_x4(ahi[i][0], ahi[i][1], ahi[i][2], ahi[i][3],
                        aoffh + a_row[i] * (APITCH * 2));
                ldsm_x4(alo[i][0], alo[i][1], alo[i][2], alo[i][3],
                        aoffl + a_row[i] * (APITCH * 2));
            }
            uint32_t bhi[4][4], blo[4][4];
            uint32_t bkrow = (buf * 32 + ks * 16 + b_k) * (BPITCH * 2);
#pragma unroll
            for (int p = 0; p < 4; p++) {
                ldsm_x4_t(bhi[p][0], bhi[p][1], bhi[p][2], bhi[p][3],
                          sBhi + bkrow + b_n[p] * 2);
                ldsm_x4_t(blo[p][0], blo[p][1], blo[p][2], blo[p][3],
                          sBlo + bkrow + b_n[p] * 2);
            }
#pragma unroll
            for (int i = 0; i < 2; i++) {
#pragma unroll
                for (int p = 0; p < 4; p++) {
#pragma unroll
                    for (int t = 0; t < 2; t++) {
                        int j = p * 2 + t;
                        uint32_t b0h = bhi[p][t * 2], b1h = bhi[p][t * 2 + 1];
                        uint32_t b0l = blo[p][t * 2], b1l = blo[p][t * 2 + 1];
                        mma_bf16(acc[i][j], ahi[i], b0h, b1h);
                        mma_bf16(acc[i][j], ahi[i], b0l, b1l);
                        mma_bf16(acc[i][j], alo[i], b0h, b1h);
                    }
                }
            }
        }

        if (nxt) {
            int nb = buf ^ 1;
            char* base = (char*)smem;
            *(uint4*)(base + SM_AHI + ((nb * 128 + ar0) * APITCH + as0 * 8) * 2) = pah0;
            *(uint4*)(base + SM_AHI + ((nb * 128 + ar1) * APITCH + as1 * 8) * 2) = pah1;
            *(uint4*)(base + SM_ALO + ((nb * 128 + ar0) * APITCH + as0 * 8) * 2) = pal0;
            *(uint4*)(base + SM_ALO + ((nb * 128 + ar1) * APITCH + as1 * 8) * 2) = pal1;
            *(uint4*)(base + SM_BHI + ((nb * 32 + bk0) * BPITCH + bs0 * 8) * 2) = pbh0;
            *(uint4*)(base + SM_BHI + ((nb * 32 + bk1) * BPITCH + bs1 * 8) * 2) = pbh1;
            *(uint4*)(base + SM_BLO + ((nb * 32 + bk0) * BPITCH + bs0 * 8) * 2) = pbl0;
            *(uint4*)(base + SM_BLO + ((nb * 32 + bk1) * BPITCH + bs1 * 8) * 2) = pbl1;
        }
        __syncthreads();
        buf ^= 1;
    }

    int g = lane >> 2, tig = lane & 3;
#pragma unroll
    for (int i = 0; i < 2; i++) {
#pragma unroll
        for (int j = 0; j < 8; j++) {
            int col = colBase + warp_n + j * 8 + tig * 2;
            float2 bv = make_float2(0.f, 0.f);
            if (bias) bv = *(const float2*)(bias + col);
            int r0 = rowBase + warp_m + i * 16 + g;
            float2 o0 = make_float2(acc[i][j][0] + bv.x, acc[i][j][1] + bv.y);
            float2 o1 = make_float2(acc[i][j][2] + bv.x, acc[i][j][3] + bv.y);
            *(float2*)(C + (size_t)r0 * N + col) = o0;
            *(float2*)(C + (size_t)(r0 + 8) * N + col) = o1;
        }
    }
}

// ---------------------------------------------------------------------------
// Tensor-core scores GEMM (unchanged from R14).
// ---------------------------------------------------------------------------
#define SC_APITCH 40
#define SC_AHI 0
#define SC_ALO 20480
#define SC_BHI 40960
#define SC_BLO 61440
#define SC_SMEM 81920

__global__ void __launch_bounds__(256) scores_mma_kernel(
    const __nv_bfloat16* __restrict__ Qh, const __nv_bfloat16* __restrict__ Ql,
    const __nv_bfloat16* __restrict__ Kh, const __nv_bfloat16* __restrict__ Kl,
    float* __restrict__ S)
{
    extern __shared__ char smem[];
    const int KD = DPROJ;
    int tid = threadIdx.x, lane = tid & 31, warp = tid >> 5;
    int bz = blockIdx.z;
    int rowBase = blockIdx.y * 128, colBase = blockIdx.x * 128;
    if (rowBase + 127 < colBase) return;
    int warp_m = (warp >> 1) * 32, warp_n = (warp & 1) * 64;

    uint32_t sA = smem_addr_u32(smem);
    uint32_t sAhi = sA + SC_AHI, sAlo = sA + SC_ALO;
    uint32_t sBhi = sA + SC_BHI, sBlo = sA + SC_BLO;

    int q = lane >> 3, r = lane & 7;
    int a_row[2];
    a_row[0] = warp_m + (q & 1) * 8 + r;
    a_row[1] = a_row[0] + 16;
    int a_col = (q >> 1) * 8;
    int b_row[4];
#pragma unroll
    for (int p = 0; p < 4; p++) b_row[p] = warp_n + p * 16 + (q & 1) * 8 + r;

    int ch0 = tid, ch1 = tid + 256;
    int ar0 = ch0 >> 2, as0 = ch0 & 3, ar1 = ch1 >> 2, as1 = ch1 & 3;

    size_t bbase = (size_t)bz * SEQ;
    const __nv_bfloat16* Ahp0 = Qh + (bbase + rowBase + ar0) * KD + as0 * 8;
    const __nv_bfloat16* Ahp1 = Qh + (bbase + rowBase + ar1) * KD + as1 * 8;
    const __nv_bfloat16* Alp0 = Ql + (bbase + rowBase + ar0) * KD + as0 * 8;
    const __nv_bfloat16* Alp1 = Ql + (bbase + rowBase + ar1) * KD + as1 * 8;
    const __nv_bfloat16* Bhp0 = Kh + (bbase + colBase + ar0) * KD + as0 * 8;
    const __nv_bfloat16* Bhp1 = Kh + (bbase + colBase + ar1) * KD + as1 * 8;
    const __nv_bfloat16* Blp0 = Kl + (bbase + colBase + ar0) * KD + as0 * 8;
    const __nv_bfloat16* Blp1 = Kl + (bbase + colBase + ar1) * KD + as1 * 8;

    float acc[2][8][4];
#pragma unroll
    for (int i = 0; i < 2; i++)
#pragma unroll
        for (int j = 0; j < 8; j++)
#pragma unroll
            for (int v = 0; v < 4; v++) acc[i][j][v] = 0.0f;

    uint4 pah0, pah1, pal0, pal1, pbh0, pbh1, pbl0, pbl1;
    pah0 = *(const uint4*)(Ahp0); pah1 = *(const uint4*)(Ahp1);
    pal0 = *(const uint4*)(Alp0); pal1 = *(const uint4*)(Alp1);
    pbh0 = *(const uint4*)(Bhp0); pbh1 = *(const uint4*)(Bhp1);
    pbl0 = *(const uint4*)(Blp0); pbl1 = *(const uint4*)(Blp1);
    {
        char* base = (char*)smem;
        *(uint4*)(base + SC_AHI + (ar0 * SC_APITCH + as0 * 8) * 2) = pah0;
        *(uint4*)(base + SC_AHI + (ar1 * SC_APITCH + as1 * 8) * 2) = pah1;
        *(uint4*)(base + SC_ALO + (ar0 * SC_APITCH + as0 * 8) * 2) = pal0;
        *(uint4*)(base + SC_ALO + (ar1 * SC_APITCH + as1 * 8) * 2) = pal1;
        *(uint4*)(base + SC_BHI + (ar0 * SC_APITCH + as0 * 8) * 2) = pbh0;
        *(uint4*)(base + SC_BHI + (ar1 * SC_APITCH + as1 * 8) * 2) = pbh1;
        *(uint4*)(base + SC_BLO + (ar0 * SC_APITCH + as0 * 8) * 2) = pbl0;
        *(uint4*)(base + SC_BLO + (ar1 * SC_APITCH + as1 * 8) * 2) = pbl1;
    }
    __syncthreads();

    const int nTiles = KD / 32;
    int buf = 0;
    for (int kt = 0; kt < nTiles; kt++) {
        bool nxt = (kt + 1 < nTiles);
        if (nxt) {
            int ko = (kt + 1) * 32;
            pah0 = *(const uint4*)(Ahp0 + ko); pah1 = *(const uint4*)(Ahp1 + ko);
            pal0 = *(const uint4*)(Alp0 + ko); pal1 = *(const uint4*)(Alp1 + ko);
            pbh0 = *(const uint4*)(Bhp0 + ko); pbh1 = *(const uint4*)(Bhp1 + ko);
            pbl0 = *(const uint4*)(Blp0 + ko); pbl1 = *(const uint4*)(Blp1 + ko);
        }

#pragma unroll
        for (int ks = 0; ks < 2; ks++) {
            uint32_t aoffh = sAhi + ((buf * 128) * SC_APITCH + ks * 16 + a_col) * 2;
            uint32_t aoffl = sAlo + ((buf * 128) * SC_APITCH + ks * 16 + a_col) * 2;
            uint32_t ahi[2][4], alo[2][4];
#pragma unroll
            for (int i = 0; i < 2; i++) {
                ldsm_x4(ahi[i][0], ahi[i][1], ahi[i][2], ahi[i][3],
                        aoffh + a_row[i] * (SC_APITCH * 2));
                ldsm_x4(alo[i][0], alo[i][1], alo[i][2], alo[i][3],
                        aoffl + a_row[i] * (SC_APITCH * 2));
            }
            uint32_t boffh = sBhi + ((buf * 128) * SC_APITCH + ks * 16 + a_col) * 2;
            uint32_t boffl = sBlo + ((buf * 128) * SC_APITCH + ks * 16 + a_col) * 2;
            uint32_t bhi[4][4], blo[4][4];
#pragma unroll
            for (int p = 0; p < 4; p++) {
                ldsm_x4(bhi[p][0], bhi[p][1], bhi[p][2], bhi[p][3],
                        boffh + b_row[p] * (SC_APITCH * 2));
                ldsm_x4(blo[p][0], blo[p][1], blo[p][2], blo[p][3],
                        boffl + b_row[p] * (SC_APITCH * 2));
            }
#pragma unroll
            for (int i = 0; i < 2; i++) {
#pragma unroll
                for (int p = 0; p < 4; p++) {
#pragma unroll
                    for (int t = 0; t < 2; t++) {
                        int j = p * 2 + t;
                        uint32_t b0h = bhi[p][t], b1h = bhi[p][t + 2];
                        uint32_t b0l = blo[p][t], b1l = blo[p][t + 2];
                        mma_bf16(acc[i][j], ahi[i], b0h, b1h);
                        mma_bf16(acc[i][j], ahi[i], b0l, b1l);
                        mma_bf16(acc[i][j], alo[i], b0h, b1h);
                    }
                }
            }
        }

        if (nxt) {
            int nb = buf ^ 1;
            char* base = (char*)smem;
            *(uint4*)(base + SC_AHI + ((nb * 128 + ar0) * SC_APITCH + as0 * 8) * 2) = pah0;
            *(uint4*)(base + SC_AHI + ((nb * 128 + ar1) * SC_APITCH + as1 * 8) * 2) = pah1;
            *(uint4*)(base + SC_ALO + ((nb * 128 + ar0) * SC_APITCH + as0 * 8) * 2) = pal0;
            *(uint4*)(base + SC_ALO + ((nb * 128 + ar1) * SC_APITCH + as1 * 8) * 2) = pal1;
            *(uint4*)(base + SC_BHI + ((nb * 128 + ar0) * SC_APITCH + as0 * 8) * 2) = pbh0;
            *(uint4*)(base + SC_BHI + ((nb * 128 + ar1) * SC_APITCH + as1 * 8) * 2) = pbh1;
            *(uint4*)(base + SC_BLO + ((nb * 128 + ar0) * SC_APITCH + as0 * 8) * 2) = pbl0;
            *(uint4*)(base + SC_BLO + ((nb * 128 + ar1) * SC_APITCH + as1 * 8) * 2) = pbl1;
        }
        __syncthreads();
        buf ^= 1;
    }

    float* Sb = S + (size_t)bz * SEQ * SEQ;
    int g = lane >> 2, tig = lane & 3;
#pragma unroll
    for (int i = 0; i < 2; i++) {
#pragma unroll
        for (int j = 0; j < 8; j++) {
            int col = colBase + warp_n + j * 8 + tig * 2;
            int r0 = rowBase + warp_m + i * 16 + g;
            *(float2*)(Sb + (size_t)r0 * SEQ + col) =
                make_float2(acc[i][j][0], acc[i][j][1]);
            *(float2*)(Sb + (size_t)(r0 + 8) * SEQ + col) =
                make_float2(acc[i][j][2], acc[i][j][3]);
        }
    }
}

// ---------------------------------------------------------------------------
// Causal row softmax: reads fp32 scores, writes bf16 (hi, lo) probabilities.
// ---------------------------------------------------------------------------
__global__ void softmax_causal_kernel()
{
    int r = blockIdx.x, b = blockIdx.y;
    size_t rowoff = ((size_t)b * SEQ + r) * SEQ;
    const float* row = g_S + rowoff;
    int len = r + 1;
    int tid = threadIdx.x;
    __shared__ float buf[SEQ];
    __shared__ float red[256];
    const float inv = rsqrtf(512.0f);

    float m = -3.4e38f;
    for (int i = tid; i < len; i += 256) m = fmaxf(m, row[i]);
    red[tid] = m; __syncthreads();
    for (int s = 128; s; s >>= 1) { if (tid < s) red[tid] = fmaxf(red[tid], red[tid + s]); __syncthreads(); }
    m = red[0] * inv;
    __syncthreads();

    float ssum = 0.0f;
    for (int i = tid; i < len; i += 256) {
        float e = __expf(row[i] * inv - m);
        buf[i] = e;
        ssum += e;
    }
    red[tid] = ssum; __syncthreads();
    for (int s = 128; s; s >>= 1) { if (tid < s) red[tid] += red[tid + s]; __syncthreads(); }
    float denom = 1.0f / red[0];
    __syncthreads();

    for (int i = tid; i < SEQ; i += 256) {
        float v = (i < len) ? buf[i] * denom : 0.0f;
        __nv_bfloat16 hi = __float2bfloat16(v);
        __nv_bfloat16 lo = __float2bfloat16(v - __bfloat162float(hi));
        g_Phi[rowoff + i] = hi;
        g_Plo[rowoff + i] = lo;
    }
}

// ---------------------------------------------------------------------------
// Prefix pooling + h0 (reads fp32 feat).
// ---------------------------------------------------------------------------
__global__ void pool_kernel(const float* __restrict__ Wscore,
                            const float* __restrict__ Wp2h,
                            const float* __restrict__ bp2h)
{
    int b = blockIdx.x;
    const float* feat = g_feat + (size_t)b * SEQ * DPROJ;
    __shared__ float wsc[512];
    __shared__ float sc[512];
    __shared__ float pooled[512];
    __shared__ float red[256];
    int tid = threadIdx.x;

    for (int i = tid; i < 512; i += 256) wsc[i] = Wscore[i];
    __syncthreads();

    int w = tid >> 5, l = tid & 31;
    for (int u = w; u < ASSIST; u += 8) {
        float s = 0.0f;
        for (int p = l; p < DPROJ; p += 32)
            s = fmaf(feat[(size_t)u * DPROJ + p], wsc[p], s);
#pragma unroll
        for (int o = 16; o; o >>= 1) s += __shfl_xor_sync(0xffffffffu, s, o);
        if (l == 0) sc[u] = s;
    }
    __syncthreads();

    float m = fmaxf(sc[tid], sc[tid + 256]);
    red[tid] = m; __syncthreads();
    for (int s = 128; s; s >>= 1) { if (tid < s) red[tid] = fmaxf(red[tid], red[tid + s]); __syncthreads(); }
    m = red[0]; __syncthreads();

    float e0 = expf(sc[tid] - m), e1 = expf(sc[tid + 256] - m);
    red[tid] = e0 + e1; __syncthreads();
    for (int s = 128; s; s >>= 1) { if (tid < s) red[tid] += red[tid + s]; __syncthreads(); }
    float inv = 1.0f / red[0];
    __syncthreads();
    sc[tid] = e0 * inv; sc[tid + 256] = e1 * inv;
    __syncthreads();

    for (int p = tid; p < DPROJ; p += 256) {
        float acc = 0.0f;
        for (int u = 0; u < ASSIST; u++)
            acc = fmaf(sc[u], feat[(size_t)u * DPROJ + p], acc);
        pooled[p] = acc;
    }
    __syncthreads();

    for (int c = tid; c < DMEM; c += 256) {
        float acc = bp2h[c];
        for (int k = 0; k < DPROJ; k++)
            acc = fmaf(pooled[k], Wp2h[(size_t)k * DMEM + c], acc);
        g_h[b * DMEM + c] = tanhf(acc);
    }
}

__global__ void init_out_kernel(float* __restrict__ out, const float* __restrict__ bmem)
{
    int i = blockIdx.x * blockDim.x + threadIdx.x;
    if (i < BATCH * RUN) out[i] = bmem[0];
}

// ---------------------------------------------------------------------------
// Cluster-based sequential scan — EXACT R11 (best known).
// ---------------------------------------------------------------------------
#define SCAN_THREADS 512
#define CL 16

#define H_OFF    0
#define RH_OFF   2048
#define PART_OFF 4096
#define WM_OFF   8192
#define SCAN_SMEM 8320

__device__ __forceinline__ uint32_t mapa_rank(uint32_t saddr, uint32_t rank) {
    uint32_t r;
    asm("mapa.shared::cluster.u32 %0, %1, %2;" : "=r"(r) : "r"(saddr), "r"(rank));
    return r;
}
__device__ __forceinline__ void stc_f32(uint32_t addr, float v) {
    asm volatile("st.shared::cluster.f32 [%0], %1;" :: "r"(addr), "f"(v));
}
#define CLUSTER_SYNC() do { \
    asm volatile("barrier.cluster.arrive.aligned;" ::: "memory"); \
    asm volatile("barrier.cluster.wait.aligned;" ::: "memory"); \
} while (0)

__global__ void __launch_bounds__(SCAN_THREADS, 1) scan_cluster(
    const float* __restrict__ Uz, const float* __restrict__ Ur,
    const float* __restrict__ Uh, const float* __restrict__ Wmem,
    const float* __restrict__ Gz, const float* __restrict__ Gr,
    const float* __restrict__ Gh, float* __restrict__ out)
{
    extern __shared__ char smem[];
    float*  h_s  = (float*)(smem + H_OFF);
    float*  rh_s = (float*)(smem + RH_OFF);
    float2* part = (float2*)(smem + PART_OFF);
    float*  wm_s = (float*)(smem + WM_OFF);

    int tid = threadIdx.x;
    int c   = tid & 31;
    int seg = tid >> 5;
    int kbase = seg * 32;

    uint32_t rank;
    asm("mov.u32 %0, %%cluster_ctarank;" : "=r"(rank));
    int cg0 = (int)rank * 32;
    int gb  = blockIdx.x >> 4;

    float uz[32], ur[32], uh[32];
#pragma unroll
    for (int i = 0; i < 32; i++) {
        uz[i] = Uz[(size_t)(kbase + i) * DMEM + cg0 + c];
        ur[i] = Ur[(size_t)(kbase + i) * DMEM + cg0 + c];
        uh[i] = Uh[(size_t)(kbase + i) * DMEM + cg0 + c];
    }
    if (tid < 32) wm_s[tid] = Wmem[cg0 + tid];

    h_s[tid] = __ldcg(&g_h[(size_t)gb * DMEM + tid]);
    __syncthreads();

    uint32_t rh_base = smem_addr_u32(rh_s);
    uint32_t h_base  = smem_addr_u32(h_s);

    const float dtc = 1.0f / 1535.0f;
    float zreg = 0.0f;

    for (int t = 0; t < RUN; t++) {
        float dtv = (t == 0) ? 0.0f : dtc;

        float gA = 0.0f, gH = 0.0f;
        if (tid < 64) {
            int cc = tid & 31, mat = tid >> 5;
            const float* P = mat ? Gr : Gz;
            gA = __ldg(&P[((size_t)(gb * RUN + t)) * DMEM + cg0 + cc]);
        }
        if (tid < 32) {
            gH = __ldg(&Gh[((size_t)(gb * RUN + t)) * DMEM + cg0 + tid]);
        }

        float pz = 0.f, pr = 0.f;
        const float4* hp = (const float4*)&h_s[kbase];
#pragma unroll
        for (int i = 0; i < 8; i++) {
            float4 h4 = hp[i];
            pz = fmaf(h4.x, uz[4*i+0], pz); pr = fmaf(h4.x, ur[4*i+0], pr);
            pz = fmaf(h4.y, uz[4*i+1], pz); pr = fmaf(h4.y, ur[4*i+1], pr);
            pz = fmaf(h4.z, uz[4*i+2], pz); pr = fmaf(h4.z, ur[4*i+2], pr);
            pz = fmaf(h4.w, uz[4*i+3], pz); pr = fmaf(h4.w, ur[4*i+3], pr);
        }
        part[tid] = make_float2(pz, pr);
        __syncthreads();

        if (tid < 64) {
            int cc = tid & 31, mat = tid >> 5;
            float s = 0.0f;
#pragma unroll
            for (int sg = 0; sg < 16; sg++) {
                float2 p = part[sg * 32 + cc];
                s += mat ? p.y : p.x;
            }
            float v = gA + s;
            float sig = 1.0f / (1.0f + __expf(-v));
            if (mat == 0) {
                zreg = sig;
            } else {
                float rhv = sig * h_s[cg0 + cc];
                uint32_t a = rh_base + (uint32_t)(cg0 + cc) * 4u;
#pragma unroll
                for (int rk = 0; rk < CL; rk++)
                    stc_f32(mapa_rank(a, (uint32_t)rk), rhv);
            }
        }
        CLUSTER_SYNC();

        float ph = 0.f;
        const float4* rp = (const float4*)&rh_s[kbase];
#pragma unroll
        for (int i = 0; i < 8; i++) {
            float4 r4 = rp[i];
            ph = fmaf(r4.x, uh[4*i+0], ph);
            ph = fmaf(r4.y, uh[4*i+1], ph);
            ph = fmaf(r4.z, uh[4*i+2], ph);
            ph = fmaf(r4.w, uh[4*i+3], ph);
        }
        part[tid].x = ph;
        __syncthreads();

        if (tid < 32) {
            int cc = tid;
            float s = 0.0f;
#pragma unroll
            for (int sg = 0; sg < 16; sg++)
                s += part[sg * 32 + cc].x;
            float hh   = tanhf(gH + s);
            int   cg   = cg0 + cc;
            float hold = h_s[cg];
            float hnew = hold + zreg * (hh - hold);
            float hout = hnew + dtv * (hnew - hold);
            if (t < RUN - 1) {
                uint32_t a = h_base + (uint32_t)cg * 4u;
#pragma unroll
                for (int rk = 0; rk < CL; rk++)
                    stc_f32(mapa_rank(a, (uint32_t)rk), hout);
            }
            float lv = hout * wm_s[cc];
#pragma unroll
            for (int o = 16; o; o >>= 1)
                lv += __shfl_xor_sync(0xffffffffu, lv, o);
            if (cc == 0)
                atomicAdd(&out[gb * RUN + t], lv);
        }
        CLUSTER_SYNC();
    }
}

// ---------------------------------------------------------------------------
// Host
// ---------------------------------------------------------------------------
extern "C" void kernel_launch(void* const* d_in, const int* in_sizes, int n_in,
                              void* d_out, int out_size)
{
    const float* x      = (const float*)d_in[0];
    const float* Wq     = (const float*)d_in[1];
    const float* bq     = (const float*)d_in[2];
    const float* Wk     = (const float*)d_in[3];
    const float* bk     = (const float*)d_in[4];
    const float* Wv     = (const float*)d_in[5];
    const float* bv     = (const float*)d_in[6];
    const float* Wz     = (const float*)d_in[7];
    const float* Uz     = (const float*)d_in[8];
    const float* bz     = (const float*)d_in[9];
    const float* Wr     = (const float*)d_in[10];
    const float* Ur     = (const float*)d_in[11];
    const float* br     = (const float*)d_in[12];
    const float* Wh     = (const float*)d_in[13];
    const float* Uh     = (const float*)d_in[14];
    const float* bh     = (const float*)d_in[15];
    const float* Wmem   = (const float*)d_in[16];
    const float* bmem   = (const float*)d_in[17];
    const float* Wp2h   = (const float*)d_in[18];
    const float* bp2h   = (const float*)d_in[19];
    const float* Wscore = (const float*)d_in[20];
    (void)in_sizes; (void)n_in;
    float* out = (float*)d_out;

    float *pQ, *pK, *pV, *pS, *pF, *pGz, *pGr, *pGh;
    cudaGetSymbolAddress((void**)&pQ,  g_Q);
    cudaGetSymbolAddress((void**)&pK,  g_K);
    cudaGetSymbolAddress((void**)&pV,  g_V);
    cudaGetSymbolAddress((void**)&pS,  g_S);
    cudaGetSymbolAddress((void**)&pF,  g_feat);
    cudaGetSymbolAddress((void**)&pGz, g_Gz);
    cudaGetSymbolAddress((void**)&pGr, g_Gr);
    cudaGetSymbolAddress((void**)&pGh, g_Gh);

    __nv_bfloat16 *pxh, *pxl, *pWh, *pWl, *pPhi, *pPlo, *pVh, *pVl,
                  *pfah, *pfal, *pUwh, *pUwl;
    cudaGetSymbolAddress((void**)&pxh,  g_xhi);
    cudaGetSymbolAddress((void**)&pxl,  g_xlo);
    cudaGetSymbolAddress((void**)&pWh,  g_Whi);
    cudaGetSymbolAddress((void**)&pWl,  g_Wlo);
    cudaGetSymbolAddress((void**)&pPhi, g_Phi);
    cudaGetSymbolAddress((void**)&pPlo, g_Plo);
    cudaGetSymbolAddress((void**)&pVh,  g_Vh);
    cudaGetSymbolAddress((void**)&pVl,  g_Vl);
    cudaGetSymbolAddress((void**)&pfah, g_fah);
    cudaGetSymbolAddress((void**)&pfal, g_fal);
    cudaGetSymbolAddress((void**)&pUwh, g_Uwh);
    cudaGetSymbolAddress((void**)&pUwl, g_Uwl);

    dim3 t256(256);
    const size_t WSZ  = (size_t)DIN * DPROJ;
    const size_t QKSZ = (size_t)ROWS * DPROJ;   // 4M
    const size_t UWSZ = (size_t)DPROJ * DMEM;   // 256K

    cudaFuncSetAttribute(mma_gemm_gen,
                         cudaFuncAttributeMaxDynamicSharedMemorySize, QKV_SMEM);
    cudaFuncSetAttribute(scores_mma_kernel,
                         cudaFuncAttributeMaxDynamicSharedMemorySize, SC_SMEM);

    // split x and W into bf16 (hi, lo)
    split_kernel<<<2048, t256>>>(x,  pxh, pxl, (size_t)ROWS * DIN / 4);
    split_kernel<<<512,  t256>>>(Wq, pWh,           pWl,           WSZ / 4);
    split_kernel<<<512,  t256>>>(Wk, pWh + WSZ,     pWl + WSZ,     WSZ / 4);
    split_kernel<<<512,  t256>>>(Wv, pWh + 2 * WSZ, pWl + 2 * WSZ, WSZ / 4);

    // QKV projections (tensor cores)
    {
        dim3 g(DPROJ / 128, ROWS / 128, 1);
        mma_gemm_gen<<<g, t256, QKV_SMEM>>>(pxh, pxl, pWh,           pWl,           bq, pQ, DPROJ, DIN, 0, 0, 0, 0);
        mma_gemm_gen<<<g, t256, QKV_SMEM>>>(pxh, pxl, pWh + WSZ,     pWl + WSZ,     bk, pK, DPROJ, DIN, 0, 0, 0, 0);
        mma_gemm_gen<<<g, t256, QKV_SMEM>>>(pxh, pxl, pWh + 2 * WSZ, pWl + 2 * WSZ, bv, pV, DPROJ, DIN, 0, 0, 0, 0);
    }

    // split Q, K (reuse g_xhi region), V (own buffers)
    __nv_bfloat16* pQh = pxh;
    __nv_bfloat16* pQl = pxh + QKSZ;
    __nv_bfloat16* pKh = pxh + 2 * QKSZ;
    __nv_bfloat16* pKl = pxh + 3 * QKSZ;
    split_kernel<<<1024, t256>>>(pQ, pQh, pQl, QKSZ / 4);
    split_kernel<<<1024, t256>>>(pK, pKh, pKl, QKSZ / 4);
    split_kernel<<<1024, t256>>>(pV, pVh, pVl, QKSZ / 4);

    // scores = Q K^T (tensor cores, causal tile skip)
    {
        dim3 g(SEQ / 128, SEQ / 128, BATCH);
        scores_mma_kernel<<<g, t256, SC_SMEM>>>(pQh, pQl, pKh, pKl, pS);
    }

    // softmax -> bf16 (hi, lo) probabilities
    softmax_causal_kernel<<<dim3(SEQ, BATCH), t256>>>();

    // feat = P V (tensor cores, K-limited by causality)
    {
        dim3 g(DPROJ / 128, SEQ / 128, BATCH);
        mma_gemm_gen<<<g, t256, QKV_SMEM>>>(pPhi, pPlo, pVh, pVl, nullptr, pF,
                                            DPROJ, SEQ,
                                            (size_t)SEQ * SEQ,
                                            (size_t)SEQ * DPROJ,
                                            (size_t)SEQ * DPROJ, 1);
    }

    pool_kernel<<<BATCH, t256>>>(Wscore, Wp2h, bp2h);

    // split feat-assist (per batch -> contiguous) and Wz/Wr/Wh
    for (int b = 0; b < BATCH; b++)
        split_kernel<<<512, t256>>>(pF + ((size_t)b * SEQ + ASSIST) * DPROJ,
                                    pfah + (size_t)b * RUN * DMEM,
                                    pfal + (size_t)b * RUN * DMEM,
                                    (size_t)RUN * DMEM / 4);
    split_kernel<<<256, t256>>>(Wz, pUwh,            pUwl,            UWSZ / 4);
    split_kernel<<<256, t256>>>(Wr, pUwh + UWSZ,     pUwl + UWSZ,     UWSZ / 4);
    split_kernel<<<256, t256>>>(Wh, pUwh + 2 * UWSZ, pUwl + 2 * UWSZ, UWSZ / 4);

    // G* = feat_assist @ W* + b* (tensor cores)
    {
        dim3 g(DMEM / 128, RUN / 128, BATCH);
        size_t aS = (size_t)RUN * DMEM, cS = (size_t)RUN * DMEM;
        mma_gemm_gen<<<g, t256, QKV_SMEM>>>(pfah, pfal, pUwh,            pUwl,            bz, pGz, DMEM, DPROJ, aS, 0, cS, 0);
        mma_gemm_gen<<<g, t256, QKV_SMEM>>>(pfah, pfal, pUwh + UWSZ,     pUwl + UWSZ,     br, pGr, DMEM, DPROJ, aS, 0, cS, 0);
        mma_gemm_gen<<<g, t256, QKV_SMEM>>>(pfah, pfal, pUwh + 2 * UWSZ, pUwl + 2 * UWSZ, bh, pGh, DMEM, DPROJ, aS, 0, cS, 0);
    }

    init_out_kernel<<<(BATCH * RUN + 255) / 256, t256>>>(out, bmem);

    // cluster scan: 4 clusters x 16 CTAs x 512 threads
    cudaFuncSetAttribute(scan_cluster,
                         cudaFuncAttributeMaxDynamicSharedMemorySize, SCAN_SMEM);
    cudaFuncSetAttribute(scan_cluster,
                         cudaFuncAttributeNonPortableClusterSizeAllowed, 1);
    {
        cudaLaunchConfig_t cfg = {};
        cfg.gridDim  = dim3(64, 1, 1);
        cfg.blockDim = dim3(SCAN_THREADS, 1, 1);
        cfg.dynamicSmemBytes = SCAN_SMEM;
        cfg.stream = 0;
        cudaLaunchAttribute attrs[1];
        attrs[0].id = cudaLaunchAttributeClusterDimension;
        attrs[0].val.clusterDim.x = CL;
        attrs[0].val.clusterDim.y = 1;
        attrs[0].val.clusterDim.z = 1;
        cfg.attrs = attrs;
        cfg.numAttrs = 1;
        cudaLaunchKernelEx(&cfg, scan_cluster,
                           Uz, Ur, Uh, Wmem,
                           (const float*)pGz, (const float*)pGr,
                           (const float*)pGh, out);
    }

    (void)out_size;
}